// round 2
// baseline (speedup 1.0000x reference)
#include <cuda_runtime.h>
#include <cuda_bf16.h>
#include <stdint.h>

#define N_NODES 100000
#define N_EDGES 1600000
#define DIM 128
#define SCAN_B 1024
#define SCAN_NB ((N_NODES + SCAN_B - 1) / SCAN_B)   // 98

// ---------------- scratch (no allocations allowed) ----------------
__device__ int   g_deg[N_NODES];
__device__ int   g_off[N_NODES];
__device__ int   g_cur[N_NODES];
__device__ int   g_bsums[SCAN_NB];
__device__ int   g_srcs[N_EDGES];          // edge sources grouped by dst (CSR)
__device__ float g_bufA[(size_t)N_NODES * DIM];
__device__ float g_bufB[(size_t)N_NODES * DIM];

// ---------------- CSR construction ----------------
__global__ void k_zero_deg() {
    int i = blockIdx.x * blockDim.x + threadIdx.x;
    if (i < N_NODES) g_deg[i] = 0;
}

__global__ void k_hist(const int* __restrict__ ei) {
    int e = blockIdx.x * blockDim.x + threadIdx.x;
    if (e < N_EDGES) {
        int d = ei[N_EDGES + e];   // dst row
        if (d >= 0 && d < N_NODES) atomicAdd(&g_deg[d], 1);
    }
}

// block-wise inclusive scan -> exclusive offsets (local), block sums out
__global__ void k_scan1() {
    __shared__ int s[SCAN_B];
    int tid = threadIdx.x;
    int i = blockIdx.x * SCAN_B + tid;
    int v = (i < N_NODES) ? g_deg[i] : 0;
    s[tid] = v;
    __syncthreads();
    #pragma unroll
    for (int d = 1; d < SCAN_B; d <<= 1) {
        int t = (tid >= d) ? s[tid - d] : 0;
        __syncthreads();
        s[tid] += t;
        __syncthreads();
    }
    if (i < N_NODES) g_off[i] = s[tid] - v;   // exclusive within block
    if (tid == SCAN_B - 1) g_bsums[blockIdx.x] = s[tid];
}

__global__ void k_scan2() {
    __shared__ int base;
    int tid = threadIdx.x;
    if (tid == 0) {
        int b = 0;
        for (int k = 0; k < (int)blockIdx.x; ++k) b += g_bsums[k];
        base = b;
    }
    __syncthreads();
    int i = blockIdx.x * SCAN_B + tid;
    if (i < N_NODES) {
        int o = g_off[i] + base;
        g_off[i] = o;
        g_cur[i] = o;
    }
}

__global__ void k_scatter(const int* __restrict__ ei) {
    int e = blockIdx.x * blockDim.x + threadIdx.x;
    if (e < N_EDGES) {
        int d = ei[N_EDGES + e];
        int s = ei[e];
        if (d >= 0 && d < N_NODES && s >= 0 && s < N_NODES) {
            int pos = atomicAdd(&g_cur[d], 1);
            g_srcs[pos] = s;
        }
    }
}

// ---------------- aggregation: t[i] = x[i] + sum_{j->i} x[j] ----------------
// one warp per node; lane handles 4 consecutive floats (float4)
__global__ void k_aggregate(const float* __restrict__ x, float* __restrict__ t) {
    int gw = (blockIdx.x * blockDim.x + threadIdx.x) >> 5;
    int lane = threadIdx.x & 31;
    if (gw >= N_NODES) return;
    int beg = g_off[gw];
    int end = beg + g_deg[gw];
    const float4* xr = (const float4*)(x + (size_t)gw * DIM) + lane;
    float4 acc = __ldg(xr);     // self term (1+eps)*x_i with eps=0
    for (int e = beg; e < end; ++e) {
        int s = g_srcs[e];
        float4 v = __ldg((const float4*)(x + (size_t)s * DIM) + lane);
        acc.x += v.x; acc.y += v.y; acc.z += v.z; acc.w += v.w;
    }
    ((float4*)(t + (size_t)gw * DIM))[lane] = acc;
}

// ---------------- GEMM: C[N,DOUT] = T[N,128] @ W[128,DOUT] + b, optional relu
// 256 threads, tile 64 rows; W fully resident in smem.
template <int DOUT, bool RELU>
__global__ void k_gemm(const float* __restrict__ T, const float* __restrict__ W,
                       const float* __restrict__ bias, float* __restrict__ C) {
    extern __shared__ float smem[];
    float* sW = smem;                 // [128 * DOUT]
    float* sT = smem + 128 * DOUT;    // [64 * 128]

    int tid = threadIdx.x;
    int rowBase = blockIdx.x * 64;

    // load W
    {
        const int n4 = (128 * DOUT) / 4;
        const float4* W4 = (const float4*)W;
        float4* sW4 = (float4*)sW;
        for (int i = tid; i < n4; i += 256) sW4[i] = W4[i];
    }
    // load T tile (64 rows x 128), zero-pad out of range
    {
        float4* sT4 = (float4*)sT;
        for (int i = tid; i < 64 * 32; i += 256) {
            int r = i >> 5;
            int c4 = i & 31;
            int row = rowBase + r;
            float4 v = make_float4(0.f, 0.f, 0.f, 0.f);
            if (row < N_NODES)
                v = __ldg((const float4*)(T + (size_t)row * 128) + c4);
            sT4[i] = v;
        }
    }
    __syncthreads();

    float acc[4][8];
    #pragma unroll
    for (int i = 0; i < 4; ++i)
        #pragma unroll
        for (int j = 0; j < 8; ++j) acc[i][j] = 0.f;

    if (DOUT == 128) {
        // 256 threads = 16 colgroups x 16 rowgroups; 4 rows x 8 cols each
        int tc = tid % 16;
        int tr = tid / 16;
        int r0 = tr * 4;
        int c0 = tc * 8;
        #pragma unroll 4
        for (int k = 0; k < 128; ++k) {
            float4 b0 = *(const float4*)(sW + k * DOUT + c0);
            float4 b1 = *(const float4*)(sW + k * DOUT + c0 + 4);
            float a[4];
            a[0] = sT[(r0 + 0) * 128 + k];
            a[1] = sT[(r0 + 1) * 128 + k];
            a[2] = sT[(r0 + 2) * 128 + k];
            a[3] = sT[(r0 + 3) * 128 + k];
            #pragma unroll
            for (int i = 0; i < 4; ++i) {
                acc[i][0] += a[i] * b0.x; acc[i][1] += a[i] * b0.y;
                acc[i][2] += a[i] * b0.z; acc[i][3] += a[i] * b0.w;
                acc[i][4] += a[i] * b1.x; acc[i][5] += a[i] * b1.y;
                acc[i][6] += a[i] * b1.z; acc[i][7] += a[i] * b1.w;
            }
        }
        float bb[8];
        #pragma unroll
        for (int j = 0; j < 8; ++j) bb[j] = bias[c0 + j];
        #pragma unroll
        for (int i = 0; i < 4; ++i) {
            int row = rowBase + r0 + i;
            if (row >= N_NODES) break;
            float v[8];
            #pragma unroll
            for (int j = 0; j < 8; ++j) {
                float t = acc[i][j] + bb[j];
                v[j] = RELU ? fmaxf(t, 0.f) : t;
            }
            float* cp = C + (size_t)row * DOUT + c0;
            *(float4*)cp = make_float4(v[0], v[1], v[2], v[3]);
            *(float4*)(cp + 4) = make_float4(v[4], v[5], v[6], v[7]);
        }
    } else {
        // DOUT == 64: 256 threads = 8 colgroups x 32 rowgroups; 2 rows x 8 cols
        int tc2 = tid % 8;
        int tr2 = tid / 8;          // 0..31
        int rr0 = tr2 * 2;          // rows 0..62
        int cc0 = tc2 * 8;
        #pragma unroll 4
        for (int k = 0; k < 128; ++k) {
            float4 b0 = *(const float4*)(sW + k * DOUT + cc0);
            float4 b1 = *(const float4*)(sW + k * DOUT + cc0 + 4);
            float a[2];
            a[0] = sT[(rr0 + 0) * 128 + k];
            a[1] = sT[(rr0 + 1) * 128 + k];
            #pragma unroll
            for (int i = 0; i < 2; ++i) {
                acc[i][0] += a[i] * b0.x; acc[i][1] += a[i] * b0.y;
                acc[i][2] += a[i] * b0.z; acc[i][3] += a[i] * b0.w;
                acc[i][4] += a[i] * b1.x; acc[i][5] += a[i] * b1.y;
                acc[i][6] += a[i] * b1.z; acc[i][7] += a[i] * b1.w;
            }
        }
        float bb[8];
        #pragma unroll
        for (int j = 0; j < 8; ++j) bb[j] = bias[cc0 + j];
        #pragma unroll
        for (int i = 0; i < 2; ++i) {
            int row = rowBase + rr0 + i;
            if (row >= N_NODES) continue;
            float v[8];
            #pragma unroll
            for (int j = 0; j < 8; ++j) {
                float t = acc[i][j] + bb[j];
                v[j] = RELU ? fmaxf(t, 0.f) : t;
            }
            float* cp = C + (size_t)row * DOUT + cc0;
            *(float4*)cp = make_float4(v[0], v[1], v[2], v[3]);
            *(float4*)(cp + 4) = make_float4(v[4], v[5], v[6], v[7]);
        }
    }
}

// ---------------- launch ----------------
extern "C" void kernel_launch(void* const* d_in, const int* in_sizes, int n_in,
                              void* d_out, int out_size) {
    const float* x  = (const float*)d_in[0];
    const int*   ei = (const int*)d_in[1];     // int32 edge_index [2, E]
    const float* W1 = (const float*)d_in[2];
    const float* b1 = (const float*)d_in[3];
    const float* Wm = (const float*)d_in[4];
    const float* bm = (const float*)d_in[5];
    const float* W2 = (const float*)d_in[6];
    const float* b2 = (const float*)d_in[7];
    float* out = (float*)d_out;

    static bool attrDone = false;
    if (!attrDone) {
        cudaFuncSetAttribute(k_gemm<128, true>,
                             cudaFuncAttributeMaxDynamicSharedMemorySize,
                             (128 * 128 + 64 * 128) * 4);
        cudaFuncSetAttribute(k_gemm<64, false>,
                             cudaFuncAttributeMaxDynamicSharedMemorySize,
                             (128 * 64 + 64 * 128) * 4);
        attrDone = true;
    }

    float* bufA = nullptr; float* bufB = nullptr;
    cudaGetSymbolAddress((void**)&bufA, g_bufA);
    cudaGetSymbolAddress((void**)&bufB, g_bufB);

    // ---- CSR build (once; shared by all 3 layers) ----
    k_zero_deg<<<(N_NODES + 255) / 256, 256>>>();
    k_hist<<<(N_EDGES + 255) / 256, 256>>>(ei);
    k_scan1<<<SCAN_NB, SCAN_B>>>();
    k_scan2<<<SCAN_NB, SCAN_B>>>();
    k_scatter<<<(N_EDGES + 255) / 256, 256>>>(ei);

    const int aggBlocks = (N_NODES + 7) / 8;   // 8 warps per 256-thr block
    const int gemmBlocks = (N_NODES + 63) / 64;
    const int smem128 = (128 * 128 + 64 * 128) * 4;
    const int smem64  = (128 * 64 + 64 * 128) * 4;

    // layer 1: agg(x) -> A ; gemm(A, W1) + relu -> B
    k_aggregate<<<aggBlocks, 256>>>(x, bufA);
    k_gemm<128, true><<<gemmBlocks, 256, smem128>>>(bufA, W1, b1, bufB);

    // layer 2: agg(B) -> A ; gemm(A, Wm) + relu -> B
    k_aggregate<<<aggBlocks, 256>>>(bufB, bufA);
    k_gemm<128, true><<<gemmBlocks, 256, smem128>>>(bufA, Wm, bm, bufB);

    // layer 3: agg(B) -> A ; gemm(A, W2) -> out
    k_aggregate<<<aggBlocks, 256>>>(bufB, bufA);
    k_gemm<64, false><<<gemmBlocks, 256, smem64>>>(bufA, W2, b2, out);

    (void)in_sizes; (void)n_in; (void)out_size;
}

// round 3
// speedup vs baseline: 1.1289x; 1.1289x over previous
#include <cuda_runtime.h>
#include <cuda_bf16.h>
#include <stdint.h>

#define N_NODES 100000
#define N_EDGES 1600000
#define DIM 128
#define SCAN_B 1024
#define SCAN_NB ((N_NODES + SCAN_B - 1) / SCAN_B)   // 98

// ---------------- scratch (no allocations allowed) ----------------
__device__ int   g_deg[N_NODES];
__device__ int   g_off[N_NODES];
__device__ int   g_cur[N_NODES];
__device__ int   g_bsums[SCAN_NB];
__device__ int   g_srcs[N_EDGES];          // edge sources grouped by dst (CSR)
__device__ float g_bufA[(size_t)N_NODES * DIM];
__device__ float g_bufB[(size_t)N_NODES * DIM];

// ---------------- CSR construction ----------------
__global__ void k_zero_deg() {
    int i = blockIdx.x * blockDim.x + threadIdx.x;
    if (i < N_NODES) g_deg[i] = 0;
}

__global__ void k_hist(const int* __restrict__ ei) {
    int e = blockIdx.x * blockDim.x + threadIdx.x;
    if (e < N_EDGES) {
        int d = ei[N_EDGES + e];   // dst row
        if (d >= 0 && d < N_NODES) atomicAdd(&g_deg[d], 1);
    }
}

__global__ void k_scan1() {
    __shared__ int s[SCAN_B];
    int tid = threadIdx.x;
    int i = blockIdx.x * SCAN_B + tid;
    int v = (i < N_NODES) ? g_deg[i] : 0;
    s[tid] = v;
    __syncthreads();
    #pragma unroll
    for (int d = 1; d < SCAN_B; d <<= 1) {
        int t = (tid >= d) ? s[tid - d] : 0;
        __syncthreads();
        s[tid] += t;
        __syncthreads();
    }
    if (i < N_NODES) g_off[i] = s[tid] - v;   // exclusive within block
    if (tid == SCAN_B - 1) g_bsums[blockIdx.x] = s[tid];
}

__global__ void k_scan2() {
    __shared__ int base;
    int tid = threadIdx.x;
    if (tid == 0) {
        int b = 0;
        for (int k = 0; k < (int)blockIdx.x; ++k) b += g_bsums[k];
        base = b;
    }
    __syncthreads();
    int i = blockIdx.x * SCAN_B + tid;
    if (i < N_NODES) {
        int o = g_off[i] + base;
        g_off[i] = o;
        g_cur[i] = o;
    }
}

__global__ void k_scatter(const int* __restrict__ ei) {
    int e = blockIdx.x * blockDim.x + threadIdx.x;
    if (e < N_EDGES) {
        int d = ei[N_EDGES + e];
        int s = ei[e];
        if (d >= 0 && d < N_NODES && s >= 0 && s < N_NODES) {
            int pos = atomicAdd(&g_cur[d], 1);
            g_srcs[pos] = s;
        }
    }
}

// ---------------- GEMM: Y[N,DOUT] = X[N,128] @ W[128,DOUT]  (no bias) -------
// Packed f32x2 FMA (Blackwell FFMA2, 2x fp32 throughput).
// Tile: 128 rows per block. Micro-tile: 8 rows x 8 cols per thread.
// THREADS = DOUT*2 (256 for DOUT=128, 128 for DOUT=64).
template <int DOUT>
__global__ void k_gemm2(const float* __restrict__ X, const float* __restrict__ W,
                        float* __restrict__ Y) {
    constexpr int THREADS = DOUT * 2;
    constexpr int TC = DOUT / 8;           // col groups
    extern __shared__ float smem[];
    float* sW = smem;                      // [128 * DOUT]
    float* sT = smem + 128 * DOUT;         // [128 * 128]

    int tid = threadIdx.x;
    int rowBase = blockIdx.x * 128;

    // load W
    for (int i = tid; i < (128 * DOUT) / 4; i += THREADS)
        ((float4*)sW)[i] = ((const float4*)W)[i];
    // load X tile (128 rows x 128 cols), zero-pad
    for (int i = tid; i < 128 * 32; i += THREADS) {
        int r = i >> 5, c4 = i & 31;
        int row = rowBase + r;
        float4 v = make_float4(0.f, 0.f, 0.f, 0.f);
        if (row < N_NODES)
            v = __ldg((const float4*)(X + (size_t)row * 128) + c4);
        ((float4*)sT)[i] = v;
    }
    __syncthreads();

    int tc = tid % TC, tr = tid / TC;      // tr in 0..15
    int c0 = tc * 8, r0 = tr * 8;

    unsigned long long acc[8][4];
    #pragma unroll
    for (int i = 0; i < 8; ++i)
        #pragma unroll
        for (int j = 0; j < 4; ++j) acc[i][j] = 0ull;

    #pragma unroll 2
    for (int k = 0; k < 128; ++k) {
        // 8 W cols at c0 -> 4 packed f32x2 operands
        ulonglong2 w01 = *(const ulonglong2*)(sW + k * DOUT + c0);
        ulonglong2 w23 = *(const ulonglong2*)(sW + k * DOUT + c0 + 4);
        unsigned long long wp0 = w01.x, wp1 = w01.y, wp2 = w23.x, wp3 = w23.y;
        #pragma unroll
        for (int i = 0; i < 8; ++i) {
            unsigned int ab = __float_as_uint(sT[(r0 + i) * 128 + k]);
            unsigned long long aa;
            asm("mov.b64 %0, {%1, %1};" : "=l"(aa) : "r"(ab));
            asm("fma.rn.f32x2 %0, %1, %2, %0;" : "+l"(acc[i][0]) : "l"(aa), "l"(wp0));
            asm("fma.rn.f32x2 %0, %1, %2, %0;" : "+l"(acc[i][1]) : "l"(aa), "l"(wp1));
            asm("fma.rn.f32x2 %0, %1, %2, %0;" : "+l"(acc[i][2]) : "l"(aa), "l"(wp2));
            asm("fma.rn.f32x2 %0, %1, %2, %0;" : "+l"(acc[i][3]) : "l"(aa), "l"(wp3));
        }
    }

    // epilogue: unpack, store
    #pragma unroll
    for (int i = 0; i < 8; ++i) {
        int row = rowBase + r0 + i;
        if (row >= N_NODES) break;
        float v[8];
        #pragma unroll
        for (int j = 0; j < 4; ++j) {
            unsigned int lo, hi;
            asm("mov.b64 {%0, %1}, %2;" : "=r"(lo), "=r"(hi) : "l"(acc[i][j]));
            v[2 * j]     = __uint_as_float(lo);
            v[2 * j + 1] = __uint_as_float(hi);
        }
        float* cp = Y + (size_t)row * DOUT + c0;
        *(float4*)cp       = make_float4(v[0], v[1], v[2], v[3]);
        *(float4*)(cp + 4) = make_float4(v[4], v[5], v[6], v[7]);
    }
}

// ---------- fused aggregate + bias (+relu): out_i = act(y_i + sum_j y_j + b)
template <int D, bool RELU>
__global__ void k_agg_post(const float* __restrict__ y, const float* __restrict__ bias,
                           float* __restrict__ out) {
    int gw = (blockIdx.x * blockDim.x + threadIdx.x) >> 5;
    int lane = threadIdx.x & 31;
    if (gw >= N_NODES) return;
    int beg = g_off[gw];
    int end = beg + g_deg[gw];

    if constexpr (D == 128) {
        float4 acc = __ldg((const float4*)(y + (size_t)gw * 128) + lane);
        int e = beg;
        for (; e + 1 < end; e += 2) {
            int s0 = g_srcs[e], s1 = g_srcs[e + 1];
            float4 v0 = __ldg((const float4*)(y + (size_t)s0 * 128) + lane);
            float4 v1 = __ldg((const float4*)(y + (size_t)s1 * 128) + lane);
            acc.x += v0.x + v1.x; acc.y += v0.y + v1.y;
            acc.z += v0.z + v1.z; acc.w += v0.w + v1.w;
        }
        if (e < end) {
            int s = g_srcs[e];
            float4 v = __ldg((const float4*)(y + (size_t)s * 128) + lane);
            acc.x += v.x; acc.y += v.y; acc.z += v.z; acc.w += v.w;
        }
        float4 bb = __ldg((const float4*)bias + lane);
        acc.x += bb.x; acc.y += bb.y; acc.z += bb.z; acc.w += bb.w;
        if (RELU) {
            acc.x = fmaxf(acc.x, 0.f); acc.y = fmaxf(acc.y, 0.f);
            acc.z = fmaxf(acc.z, 0.f); acc.w = fmaxf(acc.w, 0.f);
        }
        ((float4*)(out + (size_t)gw * 128))[lane] = acc;
    } else {
        float2 acc = __ldg((const float2*)(y + (size_t)gw * 64) + lane);
        int e = beg;
        for (; e + 1 < end; e += 2) {
            int s0 = g_srcs[e], s1 = g_srcs[e + 1];
            float2 v0 = __ldg((const float2*)(y + (size_t)s0 * 64) + lane);
            float2 v1 = __ldg((const float2*)(y + (size_t)s1 * 64) + lane);
            acc.x += v0.x + v1.x; acc.y += v0.y + v1.y;
        }
        if (e < end) {
            int s = g_srcs[e];
            float2 v = __ldg((const float2*)(y + (size_t)s * 64) + lane);
            acc.x += v.x; acc.y += v.y;
        }
        float2 bb = __ldg((const float2*)bias + lane);
        acc.x += bb.x; acc.y += bb.y;
        if (RELU) { acc.x = fmaxf(acc.x, 0.f); acc.y = fmaxf(acc.y, 0.f); }
        ((float2*)(out + (size_t)gw * 64))[lane] = acc;
    }
}

// ---------------- launch ----------------
extern "C" void kernel_launch(void* const* d_in, const int* in_sizes, int n_in,
                              void* d_out, int out_size) {
    const float* x  = (const float*)d_in[0];
    const int*   ei = (const int*)d_in[1];     // int32 edge_index [2, E]
    const float* W1 = (const float*)d_in[2];
    const float* b1 = (const float*)d_in[3];
    const float* Wm = (const float*)d_in[4];
    const float* bm = (const float*)d_in[5];
    const float* W2 = (const float*)d_in[6];
    const float* b2 = (const float*)d_in[7];
    float* out = (float*)d_out;

    const int smem128 = (128 * 128 + 128 * 128) * 4;   // 128 KB
    const int smem64  = (128 * 64  + 128 * 128) * 4;   // 96 KB

    static bool attrDone = false;
    if (!attrDone) {
        cudaFuncSetAttribute(k_gemm2<128>,
                             cudaFuncAttributeMaxDynamicSharedMemorySize, smem128);
        cudaFuncSetAttribute(k_gemm2<64>,
                             cudaFuncAttributeMaxDynamicSharedMemorySize, smem64);
        attrDone = true;
    }

    float* bufA = nullptr; float* bufB = nullptr;
    cudaGetSymbolAddress((void**)&bufA, g_bufA);
    cudaGetSymbolAddress((void**)&bufB, g_bufB);

    // ---- CSR build (once; shared by all 3 layers) ----
    k_zero_deg<<<(N_NODES + 255) / 256, 256>>>();
    k_hist<<<(N_EDGES + 255) / 256, 256>>>(ei);
    k_scan1<<<SCAN_NB, SCAN_B>>>();
    k_scan2<<<SCAN_NB, SCAN_B>>>();
    k_scatter<<<(N_EDGES + 255) / 256, 256>>>(ei);

    const int aggBlocks  = (N_NODES + 7) / 8;      // 8 warps / 256-thr block
    const int gemmBlocks = (N_NODES + 127) / 128;  // 782

    // layer 1: y = x@W1 -> A ; h = relu(y + agg(y) + b1) -> B
    k_gemm2<128><<<gemmBlocks, 256, smem128>>>(x, W1, bufA);
    k_agg_post<128, true><<<aggBlocks, 256>>>(bufA, b1, bufB);

    // layer 2: y = h@Wm -> A ; h = relu(y + agg(y) + bm) -> B
    k_gemm2<128><<<gemmBlocks, 256, smem128>>>(bufB, Wm, bufA);
    k_agg_post<128, true><<<aggBlocks, 256>>>(bufA, bm, bufB);

    // layer 3: y = h@W2 (64-dim) -> A ; out = y + agg(y) + b2
    k_gemm2<64><<<gemmBlocks, 128, smem64>>>(bufB, W2, bufA);
    k_agg_post<64, false><<<aggBlocks, 256>>>(bufA, b2, out);

    (void)in_sizes; (void)n_in; (void)out_size;
}

// round 4
// speedup vs baseline: 1.2574x; 1.1138x over previous
#include <cuda_runtime.h>
#include <cuda_bf16.h>
#include <stdint.h>

#define N_NODES 100000
#define N_EDGES 1600000
#define DIM 128
#define SCAN_B 1024
#define SCAN_NB ((N_NODES + SCAN_B - 1) / SCAN_B)   // 98

// ---------------- scratch (no allocations allowed) ----------------
__device__ int   g_deg[N_NODES];
__device__ int   g_off[N_NODES];
__device__ int   g_cur[N_NODES];
__device__ int   g_bsums[SCAN_NB];
__device__ int   g_srcs[N_EDGES];          // edge sources grouped by dst (CSR)
__device__ float g_bufA[(size_t)N_NODES * DIM];
__device__ float g_bufB[(size_t)N_NODES * DIM];

// ---------------- CSR construction ----------------
__global__ void k_zero_deg() {
    int i = blockIdx.x * blockDim.x + threadIdx.x;
    if (i < N_NODES) g_deg[i] = 0;
}

__global__ void k_hist(const int* __restrict__ ei) {
    int e = blockIdx.x * blockDim.x + threadIdx.x;
    if (e < N_EDGES) {
        int d = ei[N_EDGES + e];   // dst row
        if (d >= 0 && d < N_NODES) atomicAdd(&g_deg[d], 1);
    }
}

__global__ void k_scan1() {
    __shared__ int s[SCAN_B];
    int tid = threadIdx.x;
    int i = blockIdx.x * SCAN_B + tid;
    int v = (i < N_NODES) ? g_deg[i] : 0;
    s[tid] = v;
    __syncthreads();
    #pragma unroll
    for (int d = 1; d < SCAN_B; d <<= 1) {
        int t = (tid >= d) ? s[tid - d] : 0;
        __syncthreads();
        s[tid] += t;
        __syncthreads();
    }
    if (i < N_NODES) g_off[i] = s[tid] - v;   // exclusive within block
    if (tid == SCAN_B - 1) g_bsums[blockIdx.x] = s[tid];
}

__global__ void k_scan2() {
    __shared__ int red[32];
    int tid = threadIdx.x;
    // parallel sum of g_bsums[0 .. blockIdx.x)
    int v = (tid < (int)blockIdx.x && tid < SCAN_NB) ? g_bsums[tid] : 0;
    #pragma unroll
    for (int o = 16; o > 0; o >>= 1) v += __shfl_down_sync(0xffffffffu, v, o);
    if ((tid & 31) == 0) red[tid >> 5] = v;
    __syncthreads();
    if (tid < 32) {
        int r = (tid < (int)(blockDim.x >> 5)) ? red[tid] : 0;
        #pragma unroll
        for (int o = 16; o > 0; o >>= 1) r += __shfl_down_sync(0xffffffffu, r, o);
        if (tid == 0) red[0] = r;
    }
    __syncthreads();
    int base = red[0];
    int i = blockIdx.x * SCAN_B + tid;
    if (i < N_NODES) {
        int o = g_off[i] + base;
        g_off[i] = o;
        g_cur[i] = o;
    }
}

__global__ void k_scatter(const int* __restrict__ ei) {
    int e = blockIdx.x * blockDim.x + threadIdx.x;
    if (e < N_EDGES) {
        int d = ei[N_EDGES + e];
        int s = ei[e];
        if (d >= 0 && d < N_NODES && s >= 0 && s < N_NODES) {
            int pos = atomicAdd(&g_cur[d], 1);
            g_srcs[pos] = s;
        }
    }
}

// ---------------- GEMM: Y[N,DOUT] = X[N,128] @ W[128,DOUT]  (no bias) -------
// Packed f32x2 FMA (Blackwell FFMA2). 128 threads/CTA, 96KB smem -> 2 CTA/SM.
// DOUT=128: tile 64 rows x 128 cols.  DOUT=64: tile 128 rows x 64 cols.
// Micro-tile: 8 rows x 8 cols per thread.
template <int DOUT>
__global__ void __launch_bounds__(128, 2)
k_gemm2(const float* __restrict__ X, const float* __restrict__ W,
        float* __restrict__ Y) {
    constexpr int TROWS = (DOUT == 128) ? 64 : 128;   // rows per block
    constexpr int TC = DOUT / 8;                      // col groups
    extern __shared__ float smem[];
    float* sW = smem;                      // [128 * DOUT]
    float* sT = smem + 128 * DOUT;         // [TROWS * 128]

    int tid = threadIdx.x;
    int rowBase = blockIdx.x * TROWS;

    // load W (128 x DOUT)
    for (int i = tid; i < (128 * DOUT) / 4; i += 128)
        ((float4*)sW)[i] = ((const float4*)W)[i];
    // load X tile (TROWS x 128), zero-pad
    for (int i = tid; i < TROWS * 32; i += 128) {
        int r = i >> 5, c4 = i & 31;
        int row = rowBase + r;
        float4 v = make_float4(0.f, 0.f, 0.f, 0.f);
        if (row < N_NODES)
            v = __ldg((const float4*)(X + (size_t)row * 128) + c4);
        ((float4*)sT)[i] = v;
    }
    __syncthreads();

    int tc = tid % TC, tr = tid / TC;
    int c0 = tc * 8, r0 = tr * 8;

    unsigned long long acc[8][4];
    #pragma unroll
    for (int i = 0; i < 8; ++i)
        #pragma unroll
        for (int j = 0; j < 4; ++j) acc[i][j] = 0ull;

    #pragma unroll 2
    for (int k = 0; k < 128; ++k) {
        ulonglong2 w01 = *(const ulonglong2*)(sW + k * DOUT + c0);
        ulonglong2 w23 = *(const ulonglong2*)(sW + k * DOUT + c0 + 4);
        unsigned long long wp0 = w01.x, wp1 = w01.y, wp2 = w23.x, wp3 = w23.y;
        #pragma unroll
        for (int i = 0; i < 8; ++i) {
            unsigned int ab = __float_as_uint(sT[(r0 + i) * 128 + k]);
            unsigned long long aa;
            asm("mov.b64 %0, {%1, %1};" : "=l"(aa) : "r"(ab));
            asm("fma.rn.f32x2 %0, %1, %2, %0;" : "+l"(acc[i][0]) : "l"(aa), "l"(wp0));
            asm("fma.rn.f32x2 %0, %1, %2, %0;" : "+l"(acc[i][1]) : "l"(aa), "l"(wp1));
            asm("fma.rn.f32x2 %0, %1, %2, %0;" : "+l"(acc[i][2]) : "l"(aa), "l"(wp2));
            asm("fma.rn.f32x2 %0, %1, %2, %0;" : "+l"(acc[i][3]) : "l"(aa), "l"(wp3));
        }
    }

    // epilogue: unpack, store
    #pragma unroll
    for (int i = 0; i < 8; ++i) {
        int row = rowBase + r0 + i;
        if (row >= N_NODES) break;
        float v[8];
        #pragma unroll
        for (int j = 0; j < 4; ++j) {
            unsigned int lo, hi;
            asm("mov.b64 {%0, %1}, %2;" : "=r"(lo), "=r"(hi) : "l"(acc[i][j]));
            v[2 * j]     = __uint_as_float(lo);
            v[2 * j + 1] = __uint_as_float(hi);
        }
        float* cp = Y + (size_t)row * DOUT + c0;
        *(float4*)cp       = make_float4(v[0], v[1], v[2], v[3]);
        *(float4*)(cp + 4) = make_float4(v[4], v[5], v[6], v[7]);
    }
}

// ---------- fused aggregate + bias (+relu): out_i = act(y_i + sum_j y_j + b)
template <int D, bool RELU>
__global__ void k_agg_post(const float* __restrict__ y, const float* __restrict__ bias,
                           float* __restrict__ out) {
    int gw = (blockIdx.x * blockDim.x + threadIdx.x) >> 5;
    int lane = threadIdx.x & 31;
    if (gw >= N_NODES) return;
    int beg = g_off[gw];
    int end = beg + g_deg[gw];

    if constexpr (D == 128) {
        float4 acc = __ldg((const float4*)(y + (size_t)gw * 128) + lane);
        float4 acc2 = make_float4(0.f, 0.f, 0.f, 0.f);
        int e = beg;
        for (; e + 3 < end; e += 4) {
            int s0 = g_srcs[e],     s1 = g_srcs[e + 1];
            int s2 = g_srcs[e + 2], s3 = g_srcs[e + 3];
            float4 v0 = __ldg((const float4*)(y + (size_t)s0 * 128) + lane);
            float4 v1 = __ldg((const float4*)(y + (size_t)s1 * 128) + lane);
            float4 v2 = __ldg((const float4*)(y + (size_t)s2 * 128) + lane);
            float4 v3 = __ldg((const float4*)(y + (size_t)s3 * 128) + lane);
            acc.x  += v0.x + v1.x; acc.y  += v0.y + v1.y;
            acc.z  += v0.z + v1.z; acc.w  += v0.w + v1.w;
            acc2.x += v2.x + v3.x; acc2.y += v2.y + v3.y;
            acc2.z += v2.z + v3.z; acc2.w += v2.w + v3.w;
        }
        for (; e < end; ++e) {
            int s = g_srcs[e];
            float4 v = __ldg((const float4*)(y + (size_t)s * 128) + lane);
            acc.x += v.x; acc.y += v.y; acc.z += v.z; acc.w += v.w;
        }
        acc.x += acc2.x; acc.y += acc2.y; acc.z += acc2.z; acc.w += acc2.w;
        float4 bb = __ldg((const float4*)bias + lane);
        acc.x += bb.x; acc.y += bb.y; acc.z += bb.z; acc.w += bb.w;
        if (RELU) {
            acc.x = fmaxf(acc.x, 0.f); acc.y = fmaxf(acc.y, 0.f);
            acc.z = fmaxf(acc.z, 0.f); acc.w = fmaxf(acc.w, 0.f);
        }
        ((float4*)(out + (size_t)gw * 128))[lane] = acc;
    } else {
        float2 acc = __ldg((const float2*)(y + (size_t)gw * 64) + lane);
        float2 acc2 = make_float2(0.f, 0.f);
        int e = beg;
        for (; e + 3 < end; e += 4) {
            int s0 = g_srcs[e],     s1 = g_srcs[e + 1];
            int s2 = g_srcs[e + 2], s3 = g_srcs[e + 3];
            float2 v0 = __ldg((const float2*)(y + (size_t)s0 * 64) + lane);
            float2 v1 = __ldg((const float2*)(y + (size_t)s1 * 64) + lane);
            float2 v2 = __ldg((const float2*)(y + (size_t)s2 * 64) + lane);
            float2 v3 = __ldg((const float2*)(y + (size_t)s3 * 64) + lane);
            acc.x  += v0.x + v1.x; acc.y  += v0.y + v1.y;
            acc2.x += v2.x + v3.x; acc2.y += v2.y + v3.y;
        }
        for (; e < end; ++e) {
            int s = g_srcs[e];
            float2 v = __ldg((const float2*)(y + (size_t)s * 64) + lane);
            acc.x += v.x; acc.y += v.y;
        }
        acc.x += acc2.x; acc.y += acc2.y;
        float2 bb = __ldg((const float2*)bias + lane);
        acc.x += bb.x; acc.y += bb.y;
        if (RELU) { acc.x = fmaxf(acc.x, 0.f); acc.y = fmaxf(acc.y, 0.f); }
        ((float2*)(out + (size_t)gw * 64))[lane] = acc;
    }
}

// ---------------- launch ----------------
extern "C" void kernel_launch(void* const* d_in, const int* in_sizes, int n_in,
                              void* d_out, int out_size) {
    const float* x  = (const float*)d_in[0];
    const int*   ei = (const int*)d_in[1];     // int32 edge_index [2, E]
    const float* W1 = (const float*)d_in[2];
    const float* b1 = (const float*)d_in[3];
    const float* Wm = (const float*)d_in[4];
    const float* bm = (const float*)d_in[5];
    const float* W2 = (const float*)d_in[6];
    const float* b2 = (const float*)d_in[7];
    float* out = (float*)d_out;

    const int smem128 = (128 * 128 + 64 * 128) * 4;    // 96 KB
    const int smem64  = (128 * 64  + 128 * 128) * 4;   // 96 KB

    static bool attrDone = false;
    if (!attrDone) {
        cudaFuncSetAttribute(k_gemm2<128>,
                             cudaFuncAttributeMaxDynamicSharedMemorySize, smem128);
        cudaFuncSetAttribute(k_gemm2<64>,
                             cudaFuncAttributeMaxDynamicSharedMemorySize, smem64);
        attrDone = true;
    }

    float* bufA = nullptr; float* bufB = nullptr;
    cudaGetSymbolAddress((void**)&bufA, g_bufA);
    cudaGetSymbolAddress((void**)&bufB, g_bufB);

    // ---- CSR build (once; shared by all 3 layers) ----
    k_zero_deg<<<(N_NODES + 255) / 256, 256>>>();
    k_hist<<<(N_EDGES + 255) / 256, 256>>>(ei);
    k_scan1<<<SCAN_NB, SCAN_B>>>();
    k_scan2<<<SCAN_NB, SCAN_B>>>();
    k_scatter<<<(N_EDGES + 255) / 256, 256>>>(ei);

    const int aggBlocks   = (N_NODES + 7) / 8;       // 8 warps / 256-thr block
    const int gemmB128    = (N_NODES + 63) / 64;     // 1563 (64-row tiles)
    const int gemmB64     = (N_NODES + 127) / 128;   // 782  (128-row tiles)

    // layer 1: y = x@W1 -> A ; h = relu(y + agg(y) + b1) -> B
    k_gemm2<128><<<gemmB128, 128, smem128>>>(x, W1, bufA);
    k_agg_post<128, true><<<aggBlocks, 256>>>(bufA, b1, bufB);

    // layer 2: y = h@Wm -> A ; h = relu(y + agg(y) + bm) -> B
    k_gemm2<128><<<gemmB128, 128, smem128>>>(bufB, Wm, bufA);
    k_agg_post<128, true><<<aggBlocks, 256>>>(bufA, bm, bufB);

    // layer 3: y = h@W2 (64-dim) -> A ; out = y + agg(y) + b2
    k_gemm2<64><<<gemmB64, 128, smem64>>>(bufB, W2, bufA);
    k_agg_post<64, false><<<aggBlocks, 256>>>(bufA, b2, out);

    (void)in_sizes; (void)n_in; (void)out_size;
}

// round 5
// speedup vs baseline: 1.2740x; 1.0132x over previous
#include <cuda_runtime.h>
#include <cuda_fp16.h>
#include <stdint.h>

#define N_NODES 100000
#define N_EDGES 1600000
#define DIM 128
#define SCAN_B 1024
#define SCAN_NB ((N_NODES + SCAN_B - 1) / SCAN_B)   // 98

// ---------------- scratch (no allocations allowed) ----------------
__device__ int    g_deg[N_NODES];
__device__ int    g_off[N_NODES];
__device__ int    g_cur[N_NODES];
__device__ int    g_bsums[SCAN_NB];
__device__ int    g_srcs[N_EDGES];         // edge sources grouped by dst (CSR)
__device__ float  g_bufA[(size_t)N_NODES * DIM];
__device__ float  g_bufB[(size_t)N_NODES * DIM];
__device__ __half g_bufH[(size_t)N_NODES * DIM];   // fp16 mirror of GEMM output

// ---------------- CSR construction ----------------
__global__ void k_zero_deg() {
    int i = blockIdx.x * blockDim.x + threadIdx.x;
    if (i < N_NODES) g_deg[i] = 0;
}

__global__ void k_hist(const int* __restrict__ ei) {
    int e = blockIdx.x * blockDim.x + threadIdx.x;
    if (e < N_EDGES) {
        int d = ei[N_EDGES + e];   // dst row
        if (d >= 0 && d < N_NODES) atomicAdd(&g_deg[d], 1);
    }
}

__global__ void k_scan1() {
    __shared__ int s[SCAN_B];
    int tid = threadIdx.x;
    int i = blockIdx.x * SCAN_B + tid;
    int v = (i < N_NODES) ? g_deg[i] : 0;
    s[tid] = v;
    __syncthreads();
    #pragma unroll
    for (int d = 1; d < SCAN_B; d <<= 1) {
        int t = (tid >= d) ? s[tid - d] : 0;
        __syncthreads();
        s[tid] += t;
        __syncthreads();
    }
    if (i < N_NODES) g_off[i] = s[tid] - v;   // exclusive within block
    if (tid == SCAN_B - 1) g_bsums[blockIdx.x] = s[tid];
}

__global__ void k_scan2() {
    __shared__ int red[32];
    int tid = threadIdx.x;
    int v = (tid < (int)blockIdx.x && tid < SCAN_NB) ? g_bsums[tid] : 0;
    #pragma unroll
    for (int o = 16; o > 0; o >>= 1) v += __shfl_down_sync(0xffffffffu, v, o);
    if ((tid & 31) == 0) red[tid >> 5] = v;
    __syncthreads();
    if (tid < 32) {
        int r = (tid < (int)(blockDim.x >> 5)) ? red[tid] : 0;
        #pragma unroll
        for (int o = 16; o > 0; o >>= 1) r += __shfl_down_sync(0xffffffffu, r, o);
        if (tid == 0) red[0] = r;
    }
    __syncthreads();
    int base = red[0];
    int i = blockIdx.x * SCAN_B + tid;
    if (i < N_NODES) {
        int o = g_off[i] + base;
        g_off[i] = o;
        g_cur[i] = o;
    }
}

__global__ void k_scatter(const int* __restrict__ ei) {
    int e = blockIdx.x * blockDim.x + threadIdx.x;
    if (e < N_EDGES) {
        int d = ei[N_EDGES + e];
        int s = ei[e];
        if (d >= 0 && d < N_NODES && s >= 0 && s < N_NODES) {
            int pos = atomicAdd(&g_cur[d], 1);
            g_srcs[pos] = s;
        }
    }
}

// ---------------- GEMM: Y[N,DOUT] = X[N,128] @ W[128,DOUT]  (no bias) -------
// Packed f32x2 FMA (FFMA2). 128 threads/CTA, 96KB smem -> 2 CTA/SM.
// Also writes an fp16 mirror Y16 for the gather pass.
template <int DOUT>
__global__ void __launch_bounds__(128, 2)
k_gemm2(const float* __restrict__ X, const float* __restrict__ W,
        float* __restrict__ Y, __half* __restrict__ Y16) {
    constexpr int TROWS = (DOUT == 128) ? 64 : 128;   // rows per block
    constexpr int TC = DOUT / 8;                      // col groups
    extern __shared__ float smem[];
    float* sW = smem;                      // [128 * DOUT]
    float* sT = smem + 128 * DOUT;         // [TROWS * 128]

    int tid = threadIdx.x;
    int rowBase = blockIdx.x * TROWS;

    for (int i = tid; i < (128 * DOUT) / 4; i += 128)
        ((float4*)sW)[i] = ((const float4*)W)[i];
    for (int i = tid; i < TROWS * 32; i += 128) {
        int r = i >> 5, c4 = i & 31;
        int row = rowBase + r;
        float4 v = make_float4(0.f, 0.f, 0.f, 0.f);
        if (row < N_NODES)
            v = __ldg((const float4*)(X + (size_t)row * 128) + c4);
        ((float4*)sT)[i] = v;
    }
    __syncthreads();

    int tc = tid % TC, tr = tid / TC;
    int c0 = tc * 8, r0 = tr * 8;

    unsigned long long acc[8][4];
    #pragma unroll
    for (int i = 0; i < 8; ++i)
        #pragma unroll
        for (int j = 0; j < 4; ++j) acc[i][j] = 0ull;

    #pragma unroll 2
    for (int k = 0; k < 128; ++k) {
        ulonglong2 w01 = *(const ulonglong2*)(sW + k * DOUT + c0);
        ulonglong2 w23 = *(const ulonglong2*)(sW + k * DOUT + c0 + 4);
        unsigned long long wp0 = w01.x, wp1 = w01.y, wp2 = w23.x, wp3 = w23.y;
        #pragma unroll
        for (int i = 0; i < 8; ++i) {
            unsigned int ab = __float_as_uint(sT[(r0 + i) * 128 + k]);
            unsigned long long aa;
            asm("mov.b64 %0, {%1, %1};" : "=l"(aa) : "r"(ab));
            asm("fma.rn.f32x2 %0, %1, %2, %0;" : "+l"(acc[i][0]) : "l"(aa), "l"(wp0));
            asm("fma.rn.f32x2 %0, %1, %2, %0;" : "+l"(acc[i][1]) : "l"(aa), "l"(wp1));
            asm("fma.rn.f32x2 %0, %1, %2, %0;" : "+l"(acc[i][2]) : "l"(aa), "l"(wp2));
            asm("fma.rn.f32x2 %0, %1, %2, %0;" : "+l"(acc[i][3]) : "l"(aa), "l"(wp3));
        }
    }

    #pragma unroll
    for (int i = 0; i < 8; ++i) {
        int row = rowBase + r0 + i;
        if (row >= N_NODES) break;
        float v[8];
        #pragma unroll
        for (int j = 0; j < 4; ++j) {
            unsigned int lo, hi;
            asm("mov.b64 {%0, %1}, %2;" : "=r"(lo), "=r"(hi) : "l"(acc[i][j]));
            v[2 * j]     = __uint_as_float(lo);
            v[2 * j + 1] = __uint_as_float(hi);
        }
        float* cp = Y + (size_t)row * DOUT + c0;
        *(float4*)cp       = make_float4(v[0], v[1], v[2], v[3]);
        *(float4*)(cp + 4) = make_float4(v[4], v[5], v[6], v[7]);
        // fp16 mirror (8 halfs = 16B, aligned since c0 % 8 == 0)
        __half2 h[4];
        h[0] = __floats2half2_rn(v[0], v[1]);
        h[1] = __floats2half2_rn(v[2], v[3]);
        h[2] = __floats2half2_rn(v[4], v[5]);
        h[3] = __floats2half2_rn(v[6], v[7]);
        *(uint4*)(Y16 + (size_t)row * DOUT + c0) = *(const uint4*)h;
    }
}

// ---------- fused aggregate + bias (+relu): out_i = act(y_i + sum_j y16_j + b)
// Self term from fp32 y; neighbor gather from fp16 mirror (half the traffic).
template <int D, bool RELU>
__global__ void k_agg_post(const float* __restrict__ y,
                           const __half* __restrict__ y16,
                           const float* __restrict__ bias,
                           float* __restrict__ out) {
    int gw = (blockIdx.x * blockDim.x + threadIdx.x) >> 5;
    int lane = threadIdx.x & 31;
    if (gw >= N_NODES) return;
    int beg = g_off[gw];
    int end = beg + g_deg[gw];

    if constexpr (D == 128) {
        // lane covers feature elements [4*lane, 4*lane+3]
        float4 acc = __ldg((const float4*)(y + (size_t)gw * 128) + lane);
        float4 acc2 = make_float4(0.f, 0.f, 0.f, 0.f);
        int e = beg;
        for (; e + 3 < end; e += 4) {
            int s0 = g_srcs[e],     s1 = g_srcs[e + 1];
            int s2 = g_srcs[e + 2], s3 = g_srcs[e + 3];
            uint2 u0 = __ldg((const uint2*)(y16 + (size_t)s0 * 128) + lane);
            uint2 u1 = __ldg((const uint2*)(y16 + (size_t)s1 * 128) + lane);
            uint2 u2 = __ldg((const uint2*)(y16 + (size_t)s2 * 128) + lane);
            uint2 u3 = __ldg((const uint2*)(y16 + (size_t)s3 * 128) + lane);
            float2 a0 = __half22float2(*(const __half2*)&u0.x);
            float2 b0 = __half22float2(*(const __half2*)&u0.y);
            float2 a1 = __half22float2(*(const __half2*)&u1.x);
            float2 b1 = __half22float2(*(const __half2*)&u1.y);
            float2 a2 = __half22float2(*(const __half2*)&u2.x);
            float2 b2 = __half22float2(*(const __half2*)&u2.y);
            float2 a3 = __half22float2(*(const __half2*)&u3.x);
            float2 b3 = __half22float2(*(const __half2*)&u3.y);
            acc.x  += a0.x + a1.x; acc.y  += a0.y + a1.y;
            acc.z  += b0.x + b1.x; acc.w  += b0.y + b1.y;
            acc2.x += a2.x + a3.x; acc2.y += a2.y + a3.y;
            acc2.z += b2.x + b3.x; acc2.w += b2.y + b3.y;
        }
        for (; e < end; ++e) {
            int s = g_srcs[e];
            uint2 u = __ldg((const uint2*)(y16 + (size_t)s * 128) + lane);
            float2 a = __half22float2(*(const __half2*)&u.x);
            float2 b = __half22float2(*(const __half2*)&u.y);
            acc.x += a.x; acc.y += a.y; acc.z += b.x; acc.w += b.y;
        }
        acc.x += acc2.x; acc.y += acc2.y; acc.z += acc2.z; acc.w += acc2.w;
        float4 bb = __ldg((const float4*)bias + lane);
        acc.x += bb.x; acc.y += bb.y; acc.z += bb.z; acc.w += bb.w;
        if (RELU) {
            acc.x = fmaxf(acc.x, 0.f); acc.y = fmaxf(acc.y, 0.f);
            acc.z = fmaxf(acc.z, 0.f); acc.w = fmaxf(acc.w, 0.f);
        }
        ((float4*)(out + (size_t)gw * 128))[lane] = acc;
    } else {
        // D == 64: lane covers elements [2*lane, 2*lane+1]
        float2 acc = __ldg((const float2*)(y + (size_t)gw * 64) + lane);
        float2 acc2 = make_float2(0.f, 0.f);
        int e = beg;
        for (; e + 3 < end; e += 4) {
            int s0 = g_srcs[e],     s1 = g_srcs[e + 1];
            int s2 = g_srcs[e + 2], s3 = g_srcs[e + 3];
            unsigned u0 = __ldg((const unsigned*)(y16 + (size_t)s0 * 64) + lane);
            unsigned u1 = __ldg((const unsigned*)(y16 + (size_t)s1 * 64) + lane);
            unsigned u2 = __ldg((const unsigned*)(y16 + (size_t)s2 * 64) + lane);
            unsigned u3 = __ldg((const unsigned*)(y16 + (size_t)s3 * 64) + lane);
            float2 a0 = __half22float2(*(const __half2*)&u0);
            float2 a1 = __half22float2(*(const __half2*)&u1);
            float2 a2 = __half22float2(*(const __half2*)&u2);
            float2 a3 = __half22float2(*(const __half2*)&u3);
            acc.x  += a0.x + a1.x; acc.y  += a0.y + a1.y;
            acc2.x += a2.x + a3.x; acc2.y += a2.y + a3.y;
        }
        for (; e < end; ++e) {
            int s = g_srcs[e];
            unsigned u = __ldg((const unsigned*)(y16 + (size_t)s * 64) + lane);
            float2 a = __half22float2(*(const __half2*)&u);
            acc.x += a.x; acc.y += a.y;
        }
        acc.x += acc2.x; acc.y += acc2.y;
        float2 bb = __ldg((const float2*)bias + lane);
        acc.x += bb.x; acc.y += bb.y;
        if (RELU) { acc.x = fmaxf(acc.x, 0.f); acc.y = fmaxf(acc.y, 0.f); }
        ((float2*)(out + (size_t)gw * 64))[lane] = acc;
    }
}

// ---------------- launch ----------------
extern "C" void kernel_launch(void* const* d_in, const int* in_sizes, int n_in,
                              void* d_out, int out_size) {
    const float* x  = (const float*)d_in[0];
    const int*   ei = (const int*)d_in[1];     // int32 edge_index [2, E]
    const float* W1 = (const float*)d_in[2];
    const float* b1 = (const float*)d_in[3];
    const float* Wm = (const float*)d_in[4];
    const float* bm = (const float*)d_in[5];
    const float* W2 = (const float*)d_in[6];
    const float* b2 = (const float*)d_in[7];
    float* out = (float*)d_out;

    const int smem128 = (128 * 128 + 64 * 128) * 4;    // 96 KB
    const int smem64  = (128 * 64  + 128 * 128) * 4;   // 96 KB

    static bool attrDone = false;
    if (!attrDone) {
        cudaFuncSetAttribute(k_gemm2<128>,
                             cudaFuncAttributeMaxDynamicSharedMemorySize, smem128);
        cudaFuncSetAttribute(k_gemm2<64>,
                             cudaFuncAttributeMaxDynamicSharedMemorySize, smem64);
        attrDone = true;
    }

    float* bufA = nullptr; float* bufB = nullptr; __half* bufH = nullptr;
    cudaGetSymbolAddress((void**)&bufA, g_bufA);
    cudaGetSymbolAddress((void**)&bufB, g_bufB);
    cudaGetSymbolAddress((void**)&bufH, g_bufH);

    // ---- CSR build (once; shared by all 3 layers) ----
    k_zero_deg<<<(N_NODES + 255) / 256, 256>>>();
    k_hist<<<(N_EDGES + 255) / 256, 256>>>(ei);
    k_scan1<<<SCAN_NB, SCAN_B>>>();
    k_scan2<<<SCAN_NB, SCAN_B>>>();
    k_scatter<<<(N_EDGES + 255) / 256, 256>>>(ei);

    const int aggBlocks = (N_NODES + 7) / 8;       // 8 warps / 256-thr block
    const int gemmB128  = (N_NODES + 63) / 64;     // 1563 (64-row tiles)
    const int gemmB64   = (N_NODES + 127) / 128;   // 782  (128-row tiles)

    // layer 1: y = x@W1 -> A(+H) ; h = relu(y + agg(y) + b1) -> B
    k_gemm2<128><<<gemmB128, 128, smem128>>>(x, W1, bufA, bufH);
    k_agg_post<128, true><<<aggBlocks, 256>>>(bufA, bufH, b1, bufB);

    // layer 2: y = h@Wm -> A(+H) ; h = relu(y + agg(y) + bm) -> B
    k_gemm2<128><<<gemmB128, 128, smem128>>>(bufB, Wm, bufA, bufH);
    k_agg_post<128, true><<<aggBlocks, 256>>>(bufA, bufH, bm, bufB);

    // layer 3: y = h@W2 (64-dim) -> A(+H) ; out = y + agg(y) + b2
    k_gemm2<64><<<gemmB64, 128, smem64>>>(bufB, W2, bufA, bufH);
    k_agg_post<64, false><<<aggBlocks, 256>>>(bufA, bufH, b2, out);

    (void)in_sizes; (void)n_in; (void)out_size;
}

// round 6
// speedup vs baseline: 1.5677x; 1.2305x over previous
#include <cuda_runtime.h>
#include <cuda_fp16.h>
#include <stdint.h>

#define N_NODES 100000
#define N_EDGES 1600000
#define DIM 128
#define SCAN_B 1024
#define SCAN_NB ((N_NODES + SCAN_B - 1) / SCAN_B)   // 98

// ---------------- scratch (no allocations allowed) ----------------
__device__ int    g_deg[N_NODES];
__device__ int    g_off[N_NODES];
__device__ int    g_cur[N_NODES];
__device__ int    g_bsums[SCAN_NB];
__device__ int    g_srcs[N_EDGES];         // edge sources grouped by dst (CSR)
__device__ float  g_bufA[(size_t)N_NODES * DIM];
__device__ float  g_bufB[(size_t)N_NODES * DIM];
__device__ __half g_bufH[(size_t)N_NODES * DIM];   // fp16 mirror of GEMM output

// ---------------- CSR construction ----------------
__global__ void k_zero_deg() {
    int i = blockIdx.x * blockDim.x + threadIdx.x;
    if (i < N_NODES) g_deg[i] = 0;
}

__global__ void k_hist(const int* __restrict__ ei) {
    int e = blockIdx.x * blockDim.x + threadIdx.x;
    if (e < N_EDGES) {
        int d = ei[N_EDGES + e];   // dst row
        if (d >= 0 && d < N_NODES) atomicAdd(&g_deg[d], 1);
    }
}

__global__ void k_scan1() {
    __shared__ int s[SCAN_B];
    int tid = threadIdx.x;
    int i = blockIdx.x * SCAN_B + tid;
    int v = (i < N_NODES) ? g_deg[i] : 0;
    s[tid] = v;
    __syncthreads();
    #pragma unroll
    for (int d = 1; d < SCAN_B; d <<= 1) {
        int t = (tid >= d) ? s[tid - d] : 0;
        __syncthreads();
        s[tid] += t;
        __syncthreads();
    }
    if (i < N_NODES) g_off[i] = s[tid] - v;   // exclusive within block
    if (tid == SCAN_B - 1) g_bsums[blockIdx.x] = s[tid];
}

__global__ void k_scan2() {
    __shared__ int red[32];
    int tid = threadIdx.x;
    int v = (tid < (int)blockIdx.x && tid < SCAN_NB) ? g_bsums[tid] : 0;
    #pragma unroll
    for (int o = 16; o > 0; o >>= 1) v += __shfl_down_sync(0xffffffffu, v, o);
    if ((tid & 31) == 0) red[tid >> 5] = v;
    __syncthreads();
    if (tid < 32) {
        int r = (tid < (int)(blockDim.x >> 5)) ? red[tid] : 0;
        #pragma unroll
        for (int o = 16; o > 0; o >>= 1) r += __shfl_down_sync(0xffffffffu, r, o);
        if (tid == 0) red[0] = r;
    }
    __syncthreads();
    int base = red[0];
    int i = blockIdx.x * SCAN_B + tid;
    if (i < N_NODES) {
        int o = g_off[i] + base;
        g_off[i] = o;
        g_cur[i] = o;
    }
}

__global__ void k_scatter(const int* __restrict__ ei) {
    int e = blockIdx.x * blockDim.x + threadIdx.x;
    if (e < N_EDGES) {
        int d = ei[N_EDGES + e];
        int s = ei[e];
        if (d >= 0 && d < N_NODES && s >= 0 && s < N_NODES) {
            int pos = atomicAdd(&g_cur[d], 1);
            g_srcs[pos] = s;
        }
    }
}

// ---------------- GEMM: Y[N,DOUT] = X[N,128] @ W[128,DOUT]  (no bias) -------
// FFMA2 (fma.rn.f32x2). 256 threads/CTA, 96KB smem -> 2 CTA/SM (16 warps/SM).
// Thread map: warp owns 8 (DOUT=128) or 16 (DOUT=64) rows; lane owns 4 or 2
// cols. A-tile loads are warp-uniform broadcast LDS (conflict-free);
// W loads are coalesced LDS.128 / LDS.64.
template <int DOUT>
__global__ void __launch_bounds__(256, 2)
k_gemm2(const float* __restrict__ X, const float* __restrict__ W,
        float* __restrict__ Y, __half* __restrict__ Y16) {
    constexpr int TROWS = (DOUT == 128) ? 64 : 128;   // rows per block
    constexpr int RPW   = TROWS / 8;                  // rows per warp (8 or 16)
    extern __shared__ float smem[];
    float* sW = smem;                      // [128 * DOUT]
    float* sT = smem + 128 * DOUT;         // [TROWS * 128]

    int tid  = threadIdx.x;
    int wid  = tid >> 5;
    int lane = tid & 31;
    int rowBase = blockIdx.x * TROWS;

    for (int i = tid; i < (128 * DOUT) / 4; i += 256)
        ((float4*)sW)[i] = ((const float4*)W)[i];
    for (int i = tid; i < TROWS * 32; i += 256) {
        int r = i >> 5, c4 = i & 31;
        int row = rowBase + r;
        float4 v = make_float4(0.f, 0.f, 0.f, 0.f);
        if (row < N_NODES)
            v = __ldg((const float4*)(X + (size_t)row * 128) + c4);
        ((float4*)sT)[i] = v;
    }
    __syncthreads();

    int r0 = wid * RPW;

    if constexpr (DOUT == 128) {
        int c0 = lane * 4;
        unsigned long long acc[8][2];
        #pragma unroll
        for (int i = 0; i < 8; ++i) { acc[i][0] = 0ull; acc[i][1] = 0ull; }

        #pragma unroll 2
        for (int k = 0; k < 128; ++k) {
            ulonglong2 w = *(const ulonglong2*)(sW + k * 128 + c0);  // LDS.128
            unsigned long long wp0 = w.x, wp1 = w.y;
            #pragma unroll
            for (int i = 0; i < 8; ++i) {
                unsigned int ab = __float_as_uint(sT[(r0 + i) * 128 + k]); // bcast
                unsigned long long aa;
                asm("mov.b64 %0, {%1, %1};" : "=l"(aa) : "r"(ab));
                asm("fma.rn.f32x2 %0, %1, %2, %0;" : "+l"(acc[i][0]) : "l"(aa), "l"(wp0));
                asm("fma.rn.f32x2 %0, %1, %2, %0;" : "+l"(acc[i][1]) : "l"(aa), "l"(wp1));
            }
        }
        #pragma unroll
        for (int i = 0; i < 8; ++i) {
            int row = rowBase + r0 + i;
            if (row >= N_NODES) break;
            unsigned int l0, h0, l1, h1;
            asm("mov.b64 {%0, %1}, %2;" : "=r"(l0), "=r"(h0) : "l"(acc[i][0]));
            asm("mov.b64 {%0, %1}, %2;" : "=r"(l1), "=r"(h1) : "l"(acc[i][1]));
            float v0 = __uint_as_float(l0), v1 = __uint_as_float(h0);
            float v2 = __uint_as_float(l1), v3 = __uint_as_float(h1);
            *(float4*)(Y + (size_t)row * 128 + c0) = make_float4(v0, v1, v2, v3);
            __half2 h2[2];
            h2[0] = __floats2half2_rn(v0, v1);
            h2[1] = __floats2half2_rn(v2, v3);
            *(uint2*)(Y16 + (size_t)row * 128 + c0) = *(const uint2*)h2;
        }
    } else {
        int c0 = lane * 2;
        unsigned long long acc[16];
        #pragma unroll
        for (int i = 0; i < 16; ++i) acc[i] = 0ull;

        #pragma unroll 2
        for (int k = 0; k < 128; ++k) {
            unsigned long long wp = *(const unsigned long long*)(sW + k * 64 + c0);
            #pragma unroll
            for (int i = 0; i < 16; ++i) {
                unsigned int ab = __float_as_uint(sT[(r0 + i) * 128 + k]); // bcast
                unsigned long long aa;
                asm("mov.b64 %0, {%1, %1};" : "=l"(aa) : "r"(ab));
                asm("fma.rn.f32x2 %0, %1, %2, %0;" : "+l"(acc[i]) : "l"(aa), "l"(wp));
            }
        }
        #pragma unroll
        for (int i = 0; i < 16; ++i) {
            int row = rowBase + r0 + i;
            if (row >= N_NODES) break;
            unsigned int lo, hi;
            asm("mov.b64 {%0, %1}, %2;" : "=r"(lo), "=r"(hi) : "l"(acc[i]));
            float v0 = __uint_as_float(lo), v1 = __uint_as_float(hi);
            *(float2*)(Y + (size_t)row * 64 + c0) = make_float2(v0, v1);
            __half2 h2 = __floats2half2_rn(v0, v1);
            *(unsigned*)(Y16 + (size_t)row * 64 + c0) = *(const unsigned*)&h2;
        }
    }
}

// ---------- fused aggregate + bias (+relu): out_i = act(y_i + sum_j y16_j + b)
template <int D, bool RELU>
__global__ void k_agg_post(const float* __restrict__ y,
                           const __half* __restrict__ y16,
                           const float* __restrict__ bias,
                           float* __restrict__ out) {
    int gw = (blockIdx.x * blockDim.x + threadIdx.x) >> 5;
    int lane = threadIdx.x & 31;
    if (gw >= N_NODES) return;
    int beg = g_off[gw];
    int end = beg + g_deg[gw];

    if constexpr (D == 128) {
        float4 acc = __ldg((const float4*)(y + (size_t)gw * 128) + lane);
        float4 acc2 = make_float4(0.f, 0.f, 0.f, 0.f);
        int e = beg;
        for (; e + 3 < end; e += 4) {
            int s0 = g_srcs[e],     s1 = g_srcs[e + 1];
            int s2 = g_srcs[e + 2], s3 = g_srcs[e + 3];
            uint2 u0 = __ldg((const uint2*)(y16 + (size_t)s0 * 128) + lane);
            uint2 u1 = __ldg((const uint2*)(y16 + (size_t)s1 * 128) + lane);
            uint2 u2 = __ldg((const uint2*)(y16 + (size_t)s2 * 128) + lane);
            uint2 u3 = __ldg((const uint2*)(y16 + (size_t)s3 * 128) + lane);
            float2 a0 = __half22float2(*(const __half2*)&u0.x);
            float2 b0 = __half22float2(*(const __half2*)&u0.y);
            float2 a1 = __half22float2(*(const __half2*)&u1.x);
            float2 b1 = __half22float2(*(const __half2*)&u1.y);
            float2 a2 = __half22float2(*(const __half2*)&u2.x);
            float2 b2 = __half22float2(*(const __half2*)&u2.y);
            float2 a3 = __half22float2(*(const __half2*)&u3.x);
            float2 b3 = __half22float2(*(const __half2*)&u3.y);
            acc.x  += a0.x + a1.x; acc.y  += a0.y + a1.y;
            acc.z  += b0.x + b1.x; acc.w  += b0.y + b1.y;
            acc2.x += a2.x + a3.x; acc2.y += a2.y + a3.y;
            acc2.z += b2.x + b3.x; acc2.w += b2.y + b3.y;
        }
        for (; e < end; ++e) {
            int s = g_srcs[e];
            uint2 u = __ldg((const uint2*)(y16 + (size_t)s * 128) + lane);
            float2 a = __half22float2(*(const __half2*)&u.x);
            float2 b = __half22float2(*(const __half2*)&u.y);
            acc.x += a.x; acc.y += a.y; acc.z += b.x; acc.w += b.y;
        }
        acc.x += acc2.x; acc.y += acc2.y; acc.z += acc2.z; acc.w += acc2.w;
        float4 bb = __ldg((const float4*)bias + lane);
        acc.x += bb.x; acc.y += bb.y; acc.z += bb.z; acc.w += bb.w;
        if (RELU) {
            acc.x = fmaxf(acc.x, 0.f); acc.y = fmaxf(acc.y, 0.f);
            acc.z = fmaxf(acc.z, 0.f); acc.w = fmaxf(acc.w, 0.f);
        }
        ((float4*)(out + (size_t)gw * 128))[lane] = acc;
    } else {
        float2 acc = __ldg((const float2*)(y + (size_t)gw * 64) + lane);
        float2 acc2 = make_float2(0.f, 0.f);
        int e = beg;
        for (; e + 3 < end; e += 4) {
            int s0 = g_srcs[e],     s1 = g_srcs[e + 1];
            int s2 = g_srcs[e + 2], s3 = g_srcs[e + 3];
            unsigned u0 = __ldg((const unsigned*)(y16 + (size_t)s0 * 64) + lane);
            unsigned u1 = __ldg((const unsigned*)(y16 + (size_t)s1 * 64) + lane);
            unsigned u2 = __ldg((const unsigned*)(y16 + (size_t)s2 * 64) + lane);
            unsigned u3 = __ldg((const unsigned*)(y16 + (size_t)s3 * 64) + lane);
            float2 a0 = __half22float2(*(const __half2*)&u0);
            float2 a1 = __half22float2(*(const __half2*)&u1);
            float2 a2 = __half22float2(*(const __half2*)&u2);
            float2 a3 = __half22float2(*(const __half2*)&u3);
            acc.x  += a0.x + a1.x; acc.y  += a0.y + a1.y;
            acc2.x += a2.x + a3.x; acc2.y += a2.y + a3.y;
        }
        for (; e < end; ++e) {
            int s = g_srcs[e];
            unsigned u = __ldg((const unsigned*)(y16 + (size_t)s * 64) + lane);
            float2 a = __half22float2(*(const __half2*)&u);
            acc.x += a.x; acc.y += a.y;
        }
        acc.x += acc2.x; acc.y += acc2.y;
        float2 bb = __ldg((const float2*)bias + lane);
        acc.x += bb.x; acc.y += bb.y;
        if (RELU) { acc.x = fmaxf(acc.x, 0.f); acc.y = fmaxf(acc.y, 0.f); }
        ((float2*)(out + (size_t)gw * 64))[lane] = acc;
    }
}

// ---------------- launch ----------------
extern "C" void kernel_launch(void* const* d_in, const int* in_sizes, int n_in,
                              void* d_out, int out_size) {
    const float* x  = (const float*)d_in[0];
    const int*   ei = (const int*)d_in[1];     // int32 edge_index [2, E]
    const float* W1 = (const float*)d_in[2];
    const float* b1 = (const float*)d_in[3];
    const float* Wm = (const float*)d_in[4];
    const float* bm = (const float*)d_in[5];
    const float* W2 = (const float*)d_in[6];
    const float* b2 = (const float*)d_in[7];
    float* out = (float*)d_out;

    const int smem128 = (128 * 128 + 64 * 128) * 4;    // 96 KB
    const int smem64  = (128 * 64  + 128 * 128) * 4;   // 96 KB

    static bool initDone = false;
    static cudaStream_t s2 = nullptr;
    static cudaEvent_t evFork = nullptr, evJoin = nullptr;
    if (!initDone) {
        cudaFuncSetAttribute(k_gemm2<128>,
                             cudaFuncAttributeMaxDynamicSharedMemorySize, smem128);
        cudaFuncSetAttribute(k_gemm2<64>,
                             cudaFuncAttributeMaxDynamicSharedMemorySize, smem64);
        cudaStreamCreateWithFlags(&s2, cudaStreamNonBlocking);
        cudaEventCreateWithFlags(&evFork, cudaEventDisableTiming);
        cudaEventCreateWithFlags(&evJoin, cudaEventDisableTiming);
        initDone = true;
    }

    float* bufA = nullptr; float* bufB = nullptr; __half* bufH = nullptr;
    cudaGetSymbolAddress((void**)&bufA, g_bufA);
    cudaGetSymbolAddress((void**)&bufB, g_bufB);
    cudaGetSymbolAddress((void**)&bufH, g_bufH);

    const int aggBlocks = (N_NODES + 7) / 8;       // 8 warps / 256-thr block
    const int gemmB128  = (N_NODES + 63) / 64;     // 1563 (64-row tiles)
    const int gemmB64   = (N_NODES + 127) / 128;   // 782  (128-row tiles)

    // ---- fork: CSR build on s2, concurrent with layer-1 GEMM on default ----
    cudaEventRecord(evFork, 0);
    cudaStreamWaitEvent(s2, evFork, 0);

    k_zero_deg<<<(N_NODES + 255) / 256, 256, 0, s2>>>();
    k_hist<<<(N_EDGES + 255) / 256, 256, 0, s2>>>(ei);
    k_scan1<<<SCAN_NB, SCAN_B, 0, s2>>>();
    k_scan2<<<SCAN_NB, SCAN_B, 0, s2>>>();
    k_scatter<<<(N_EDGES + 255) / 256, 256, 0, s2>>>(ei);
    cudaEventRecord(evJoin, s2);

    // layer 1 GEMM (independent of CSR): y = x@W1 -> A(+H)
    k_gemm2<128><<<gemmB128, 256, smem128>>>(x, W1, bufA, bufH);

    // join: aggregation needs both GEMM output and CSR
    cudaStreamWaitEvent(0, evJoin, 0);

    // layer 1 agg: h = relu(y + agg(y) + b1) -> B
    k_agg_post<128, true><<<aggBlocks, 256>>>(bufA, bufH, b1, bufB);

    // layer 2
    k_gemm2<128><<<gemmB128, 256, smem128>>>(bufB, Wm, bufA, bufH);
    k_agg_post<128, true><<<aggBlocks, 256>>>(bufA, bufH, bm, bufB);

    // layer 3 (64-dim)
    k_gemm2<64><<<gemmB64, 256, smem64>>>(bufB, W2, bufA, bufH);
    k_agg_post<64, false><<<aggBlocks, 256>>>(bufA, bufH, b2, out);

    (void)in_sizes; (void)n_in; (void)out_size;
}

// round 7
// speedup vs baseline: 1.7967x; 1.1461x over previous
#include <cuda_runtime.h>
#include <cuda_fp16.h>
#include <cuda_bf16.h>
#include <stdint.h>

#define N_NODES 100000
#define N_EDGES 1600000
#define DIM 128
#define SCAN_B 1024
#define SCAN_NB ((N_NODES + SCAN_B - 1) / SCAN_B)   // 98

// ---------------- scratch (no allocations allowed) ----------------
__device__ int    g_deg[N_NODES];
__device__ int    g_off[N_NODES];
__device__ int    g_cur[N_NODES];
__device__ int    g_bsums[SCAN_NB];
__device__ int    g_srcs[N_EDGES];         // edge sources grouped by dst (CSR)
__device__ float  g_bufA[(size_t)N_NODES * DIM];
__device__ float  g_bufB[(size_t)N_NODES * DIM];
__device__ __half g_bufH[(size_t)N_NODES * DIM];   // fp16 mirror of GEMM output

// ---------------- CSR construction ----------------
__global__ void k_zero_deg() {
    int i = blockIdx.x * blockDim.x + threadIdx.x;
    if (i < N_NODES) g_deg[i] = 0;
}

__global__ void k_hist(const int* __restrict__ ei) {
    int e = blockIdx.x * blockDim.x + threadIdx.x;
    if (e < N_EDGES) {
        int d = ei[N_EDGES + e];   // dst row
        if (d >= 0 && d < N_NODES) atomicAdd(&g_deg[d], 1);
    }
}

__global__ void k_scan1() {
    __shared__ int s[SCAN_B];
    int tid = threadIdx.x;
    int i = blockIdx.x * SCAN_B + tid;
    int v = (i < N_NODES) ? g_deg[i] : 0;
    s[tid] = v;
    __syncthreads();
    #pragma unroll
    for (int d = 1; d < SCAN_B; d <<= 1) {
        int t = (tid >= d) ? s[tid - d] : 0;
        __syncthreads();
        s[tid] += t;
        __syncthreads();
    }
    if (i < N_NODES) g_off[i] = s[tid] - v;   // exclusive within block
    if (tid == SCAN_B - 1) g_bsums[blockIdx.x] = s[tid];
}

__global__ void k_scan2() {
    __shared__ int red[32];
    int tid = threadIdx.x;
    int v = (tid < (int)blockIdx.x && tid < SCAN_NB) ? g_bsums[tid] : 0;
    #pragma unroll
    for (int o = 16; o > 0; o >>= 1) v += __shfl_down_sync(0xffffffffu, v, o);
    if ((tid & 31) == 0) red[tid >> 5] = v;
    __syncthreads();
    if (tid < 32) {
        int r = (tid < (int)(blockDim.x >> 5)) ? red[tid] : 0;
        #pragma unroll
        for (int o = 16; o > 0; o >>= 1) r += __shfl_down_sync(0xffffffffu, r, o);
        if (tid == 0) red[0] = r;
    }
    __syncthreads();
    int base = red[0];
    int i = blockIdx.x * SCAN_B + tid;
    if (i < N_NODES) {
        int o = g_off[i] + base;
        g_off[i] = o;
        g_cur[i] = o;
    }
}

__global__ void k_scatter(const int* __restrict__ ei) {
    int e = blockIdx.x * blockDim.x + threadIdx.x;
    if (e < N_EDGES) {
        int d = ei[N_EDGES + e];
        int s = ei[e];
        if (d >= 0 && d < N_NODES && s >= 0 && s < N_NODES) {
            int pos = atomicAdd(&g_cur[d], 1);
            g_srcs[pos] = s;
        }
    }
}

// ---------------- tensor-core helpers ----------------
__device__ __forceinline__ unsigned cvta_s(const void* p) {
    return (unsigned)__cvta_generic_to_shared(p);
}

__device__ __forceinline__ void ldsm_x4(unsigned& r0, unsigned& r1,
                                        unsigned& r2, unsigned& r3, unsigned a) {
    asm volatile("ldmatrix.sync.aligned.m8n8.x4.shared.b16 {%0,%1,%2,%3}, [%4];"
                 : "=r"(r0), "=r"(r1), "=r"(r2), "=r"(r3) : "r"(a));
}

__device__ __forceinline__ void ldsm_x2t(unsigned& r0, unsigned& r1, unsigned a) {
    asm volatile("ldmatrix.sync.aligned.m8n8.x2.trans.shared.b16 {%0,%1}, [%2];"
                 : "=r"(r0), "=r"(r1) : "r"(a));
}

__device__ __forceinline__ void mma_bf16(float* c, unsigned a0, unsigned a1,
                                         unsigned a2, unsigned a3,
                                         unsigned b0, unsigned b1) {
    asm volatile(
        "mma.sync.aligned.m16n8k16.row.col.f32.bf16.bf16.f32 "
        "{%0,%1,%2,%3}, {%4,%5,%6,%7}, {%8,%9}, {%0,%1,%2,%3};"
        : "+f"(c[0]), "+f"(c[1]), "+f"(c[2]), "+f"(c[3])
        : "r"(a0), "r"(a1), "r"(a2), "r"(a3), "r"(b0), "r"(b1));
}

__device__ __forceinline__ unsigned pack_bf16(__nv_bfloat16 a, __nv_bfloat16 b) {
    __nv_bfloat162 p;
    p.x = a; p.y = b;
    return *reinterpret_cast<unsigned*>(&p);
}

__device__ __forceinline__ void bsplit(float f, __nv_bfloat16& h, __nv_bfloat16& l) {
    h = __float2bfloat16_rn(f);
    l = __float2bfloat16_rn(f - __bfloat162float(h));
}

// ---------------- GEMM (tensor core, bf16-split): Y = X[N,128] @ W[128,DOUT]
// 256 threads/CTA. DOUT=128: tile 64 rows, warp = (rowgroup, n-half).
// DOUT=64: tile 128 rows, warp = rowgroup. Each warp: 16 rows x 64 cols
// via 8 n-tiles of m16n8k16, 3 MMAs per tile (hi*hi + lo*hi + hi*lo).
template <int DOUT>
__global__ void __launch_bounds__(256, 2)
k_gemm_tc(const float* __restrict__ X, const float* __restrict__ W,
          float* __restrict__ Y, __half* __restrict__ Y16) {
    constexpr int TROWS = (DOUT == 128) ? 64 : 128;
    constexpr int LDA = 136;          // bf16 elems per A row (pad 8)
    constexpr int LDB = DOUT + 8;     // bf16 elems per W row (pad 8)
    extern __shared__ __nv_bfloat16 sm[];
    __nv_bfloat16* sAh = sm;
    __nv_bfloat16* sAl = sAh + TROWS * LDA;
    __nv_bfloat16* sWh = sAl + TROWS * LDA;
    __nv_bfloat16* sWl = sWh + 128 * LDB;

    int tid = threadIdx.x, wid = tid >> 5, lane = tid & 31;
    int g = lane >> 2, tg = lane & 3;
    int rowBase = blockIdx.x * TROWS;

    // A tile: TROWS x 128 f32 -> bf16 hi/lo (zero-pad OOB rows)
    for (int i = tid; i < TROWS * 32; i += 256) {
        int r = i >> 5, c4 = i & 31;
        int row = rowBase + r;
        float4 v = make_float4(0.f, 0.f, 0.f, 0.f);
        if (row < N_NODES)
            v = __ldg((const float4*)(X + (size_t)row * 128) + c4);
        __nv_bfloat16 h0, h1, h2, h3, l0, l1, l2, l3;
        bsplit(v.x, h0, l0); bsplit(v.y, h1, l1);
        bsplit(v.z, h2, l2); bsplit(v.w, h3, l3);
        int off = r * LDA + c4 * 4;
        *(uint2*)(sAh + off) = make_uint2(pack_bf16(h0, h1), pack_bf16(h2, h3));
        *(uint2*)(sAl + off) = make_uint2(pack_bf16(l0, l1), pack_bf16(l2, l3));
    }
    // W: 128 x DOUT f32 -> bf16 hi/lo (row-major [k][n], coalesced)
    for (int i = tid; i < 128 * (DOUT / 4); i += 256) {
        int k = i / (DOUT / 4), n4 = i % (DOUT / 4);
        float4 v = __ldg((const float4*)(W + (size_t)k * DOUT) + n4);
        __nv_bfloat16 h0, h1, h2, h3, l0, l1, l2, l3;
        bsplit(v.x, h0, l0); bsplit(v.y, h1, l1);
        bsplit(v.z, h2, l2); bsplit(v.w, h3, l3);
        int off = k * LDB + n4 * 4;
        *(uint2*)(sWh + off) = make_uint2(pack_bf16(h0, h1), pack_bf16(h2, h3));
        *(uint2*)(sWl + off) = make_uint2(pack_bf16(l0, l1), pack_bf16(l2, l3));
    }
    __syncthreads();

    int rg, n0;
    if constexpr (DOUT == 128) { rg = wid >> 1; n0 = (wid & 1) * 64; }
    else                       { rg = wid;      n0 = 0; }
    int r0 = rg * 16;

    float acc[8][4];
    #pragma unroll
    for (int i = 0; i < 8; ++i)
        #pragma unroll
        for (int j = 0; j < 4; ++j) acc[i][j] = 0.f;

    // lane-level ldmatrix source addresses
    int arow = r0 + (lane & 15);
    int acolo = (lane >> 4) * 8;           // 0 or 8 (k offset for matrices 2,3)
    unsigned aH = cvta_s(sAh) + (unsigned)((arow * LDA + acolo) * 2);
    unsigned aL = cvta_s(sAl) + (unsigned)((arow * LDA + acolo) * 2);
    int brow = lane & 15;                  // k-row within step
    unsigned bH = cvta_s(sWh) + (unsigned)((brow * LDB + n0) * 2);
    unsigned bL = cvta_s(sWl) + (unsigned)((brow * LDB + n0) * 2);

    #pragma unroll
    for (int ks = 0; ks < 8; ++ks) {
        int k0 = ks * 16;
        unsigned ah0, ah1, ah2, ah3, al0, al1, al2, al3;
        ldsm_x4(ah0, ah1, ah2, ah3, aH + (unsigned)(k0 * 2));
        ldsm_x4(al0, al1, al2, al3, aL + (unsigned)(k0 * 2));
        unsigned bkoff = (unsigned)(k0 * LDB * 2);
        #pragma unroll
        for (int nt = 0; nt < 8; ++nt) {
            unsigned noff = bkoff + (unsigned)(nt * 8 * 2);
            unsigned bh0, bh1, bl0, bl1;
            ldsm_x2t(bh0, bh1, bH + noff);
            ldsm_x2t(bl0, bl1, bL + noff);
            mma_bf16(acc[nt], ah0, ah1, ah2, ah3, bh0, bh1);   // hi*hi
            mma_bf16(acc[nt], al0, al1, al2, al3, bh0, bh1);   // lo*hi
            mma_bf16(acc[nt], ah0, ah1, ah2, ah3, bl0, bl1);   // hi*lo
        }
    }

    // epilogue: D frag (row g / g+8, col tg*2, tg*2+1) per n-tile
    int row0 = rowBase + r0 + g;
    int row1 = row0 + 8;
    #pragma unroll
    for (int nt = 0; nt < 8; ++nt) {
        int col = n0 + nt * 8 + tg * 2;
        if (row0 < N_NODES) {
            *(float2*)(Y + (size_t)row0 * DOUT + col) = make_float2(acc[nt][0], acc[nt][1]);
            __half2 hh = __floats2half2_rn(acc[nt][0], acc[nt][1]);
            *(unsigned*)(Y16 + (size_t)row0 * DOUT + col) = *(const unsigned*)&hh;
        }
        if (row1 < N_NODES) {
            *(float2*)(Y + (size_t)row1 * DOUT + col) = make_float2(acc[nt][2], acc[nt][3]);
            __half2 hh = __floats2half2_rn(acc[nt][2], acc[nt][3]);
            *(unsigned*)(Y16 + (size_t)row1 * DOUT + col) = *(const unsigned*)&hh;
        }
    }
}

// ---------- fused aggregate + bias (+relu): out_i = act(y_i + sum_j y16_j + b)
template <int D, bool RELU>
__global__ void k_agg_post(const float* __restrict__ y,
                           const __half* __restrict__ y16,
                           const float* __restrict__ bias,
                           float* __restrict__ out) {
    int gw = (blockIdx.x * blockDim.x + threadIdx.x) >> 5;
    int lane = threadIdx.x & 31;
    if (gw >= N_NODES) return;
    int beg = g_off[gw];
    int end = beg + g_deg[gw];

    if constexpr (D == 128) {
        float4 acc = __ldg((const float4*)(y + (size_t)gw * 128) + lane);
        float4 acc2 = make_float4(0.f, 0.f, 0.f, 0.f);
        int e = beg;
        for (; e + 3 < end; e += 4) {
            int s0 = g_srcs[e],     s1 = g_srcs[e + 1];
            int s2 = g_srcs[e + 2], s3 = g_srcs[e + 3];
            uint2 u0 = __ldg((const uint2*)(y16 + (size_t)s0 * 128) + lane);
            uint2 u1 = __ldg((const uint2*)(y16 + (size_t)s1 * 128) + lane);
            uint2 u2 = __ldg((const uint2*)(y16 + (size_t)s2 * 128) + lane);
            uint2 u3 = __ldg((const uint2*)(y16 + (size_t)s3 * 128) + lane);
            float2 a0 = __half22float2(*(const __half2*)&u0.x);
            float2 b0 = __half22float2(*(const __half2*)&u0.y);
            float2 a1 = __half22float2(*(const __half2*)&u1.x);
            float2 b1 = __half22float2(*(const __half2*)&u1.y);
            float2 a2 = __half22float2(*(const __half2*)&u2.x);
            float2 b2 = __half22float2(*(const __half2*)&u2.y);
            float2 a3 = __half22float2(*(const __half2*)&u3.x);
            float2 b3 = __half22float2(*(const __half2*)&u3.y);
            acc.x  += a0.x + a1.x; acc.y  += a0.y + a1.y;
            acc.z  += b0.x + b1.x; acc.w  += b0.y + b1.y;
            acc2.x += a2.x + a3.x; acc2.y += a2.y + a3.y;
            acc2.z += b2.x + b3.x; acc2.w += b2.y + b3.y;
        }
        for (; e < end; ++e) {
            int s = g_srcs[e];
            uint2 u = __ldg((const uint2*)(y16 + (size_t)s * 128) + lane);
            float2 a = __half22float2(*(const __half2*)&u.x);
            float2 b = __half22float2(*(const __half2*)&u.y);
            acc.x += a.x; acc.y += a.y; acc.z += b.x; acc.w += b.y;
        }
        acc.x += acc2.x; acc.y += acc2.y; acc.z += acc2.z; acc.w += acc2.w;
        float4 bb = __ldg((const float4*)bias + lane);
        acc.x += bb.x; acc.y += bb.y; acc.z += bb.z; acc.w += bb.w;
        if (RELU) {
            acc.x = fmaxf(acc.x, 0.f); acc.y = fmaxf(acc.y, 0.f);
            acc.z = fmaxf(acc.z, 0.f); acc.w = fmaxf(acc.w, 0.f);
        }
        ((float4*)(out + (size_t)gw * 128))[lane] = acc;
    } else {
        float2 acc = __ldg((const float2*)(y + (size_t)gw * 64) + lane);
        float2 acc2 = make_float2(0.f, 0.f);
        int e = beg;
        for (; e + 3 < end; e += 4) {
            int s0 = g_srcs[e],     s1 = g_srcs[e + 1];
            int s2 = g_srcs[e + 2], s3 = g_srcs[e + 3];
            unsigned u0 = __ldg((const unsigned*)(y16 + (size_t)s0 * 64) + lane);
            unsigned u1 = __ldg((const unsigned*)(y16 + (size_t)s1 * 64) + lane);
            unsigned u2 = __ldg((const unsigned*)(y16 + (size_t)s2 * 64) + lane);
            unsigned u3 = __ldg((const unsigned*)(y16 + (size_t)s3 * 64) + lane);
            float2 a0 = __half22float2(*(const __half2*)&u0);
            float2 a1 = __half22float2(*(const __half2*)&u1);
            float2 a2 = __half22float2(*(const __half2*)&u2);
            float2 a3 = __half22float2(*(const __half2*)&u3);
            acc.x  += a0.x + a1.x; acc.y  += a0.y + a1.y;
            acc2.x += a2.x + a3.x; acc2.y += a2.y + a3.y;
        }
        for (; e < end; ++e) {
            int s = g_srcs[e];
            unsigned u = __ldg((const unsigned*)(y16 + (size_t)s * 64) + lane);
            float2 a = __half22float2(*(const __half2*)&u);
            acc.x += a.x; acc.y += a.y;
        }
        acc.x += acc2.x; acc.y += acc2.y;
        float2 bb = __ldg((const float2*)bias + lane);
        acc.x += bb.x; acc.y += bb.y;
        if (RELU) { acc.x = fmaxf(acc.x, 0.f); acc.y = fmaxf(acc.y, 0.f); }
        ((float2*)(out + (size_t)gw * 64))[lane] = acc;
    }
}

// ---------------- launch ----------------
extern "C" void kernel_launch(void* const* d_in, const int* in_sizes, int n_in,
                              void* d_out, int out_size) {
    const float* x  = (const float*)d_in[0];
    const int*   ei = (const int*)d_in[1];     // int32 edge_index [2, E]
    const float* W1 = (const float*)d_in[2];
    const float* b1 = (const float*)d_in[3];
    const float* Wm = (const float*)d_in[4];
    const float* bm = (const float*)d_in[5];
    const float* W2 = (const float*)d_in[6];
    const float* b2 = (const float*)d_in[7];
    float* out = (float*)d_out;

    // smem: A(TROWS*136)*2 + W(128*(DOUT+8))*2, bf16 elems * 2 bytes
    const int smem128 = (64 * 136 * 2 + 128 * 136 * 2) * 2;   // 104448
    const int smem64  = (128 * 136 * 2 + 128 * 72 * 2) * 2;   // 106496

    static bool initDone = false;
    static cudaStream_t s2 = nullptr;
    static cudaEvent_t evFork = nullptr, evJoin = nullptr;
    if (!initDone) {
        cudaFuncSetAttribute(k_gemm_tc<128>,
                             cudaFuncAttributeMaxDynamicSharedMemorySize, smem128);
        cudaFuncSetAttribute(k_gemm_tc<64>,
                             cudaFuncAttributeMaxDynamicSharedMemorySize, smem64);
        cudaStreamCreateWithFlags(&s2, cudaStreamNonBlocking);
        cudaEventCreateWithFlags(&evFork, cudaEventDisableTiming);
        cudaEventCreateWithFlags(&evJoin, cudaEventDisableTiming);
        initDone = true;
    }

    float* bufA = nullptr; float* bufB = nullptr; __half* bufH = nullptr;
    cudaGetSymbolAddress((void**)&bufA, g_bufA);
    cudaGetSymbolAddress((void**)&bufB, g_bufB);
    cudaGetSymbolAddress((void**)&bufH, g_bufH);

    const int aggBlocks = (N_NODES + 7) / 8;       // 8 warps / 256-thr block
    const int gemmB128  = (N_NODES + 63) / 64;     // 1563 (64-row tiles)
    const int gemmB64   = (N_NODES + 127) / 128;   // 782  (128-row tiles)

    // ---- fork: CSR build on s2, concurrent with layer-1 GEMM ----
    cudaEventRecord(evFork, 0);
    cudaStreamWaitEvent(s2, evFork, 0);

    k_zero_deg<<<(N_NODES + 255) / 256, 256, 0, s2>>>();
    k_hist<<<(N_EDGES + 255) / 256, 256, 0, s2>>>(ei);
    k_scan1<<<SCAN_NB, SCAN_B, 0, s2>>>();
    k_scan2<<<SCAN_NB, SCAN_B, 0, s2>>>();
    k_scatter<<<(N_EDGES + 255) / 256, 256, 0, s2>>>(ei);
    cudaEventRecord(evJoin, s2);

    // layer 1 GEMM (independent of CSR): y = x@W1 -> A(+H)
    k_gemm_tc<128><<<gemmB128, 256, smem128>>>(x, W1, bufA, bufH);

    // join: aggregation needs both GEMM output and CSR
    cudaStreamWaitEvent(0, evJoin, 0);

    // layer 1 agg: h = relu(y + agg(y) + b1) -> B
    k_agg_post<128, true><<<aggBlocks, 256>>>(bufA, bufH, b1, bufB);

    // layer 2
    k_gemm_tc<128><<<gemmB128, 256, smem128>>>(bufB, Wm, bufA, bufH);
    k_agg_post<128, true><<<aggBlocks, 256>>>(bufA, bufH, bm, bufB);

    // layer 3 (64-dim)
    k_gemm_tc<64><<<gemmB64, 256, smem64>>>(bufB, W2, bufA, bufH);
    k_agg_post<64, false><<<aggBlocks, 256>>>(bufA, bufH, b2, out);

    (void)in_sizes; (void)n_in; (void)out_size;
}

// round 8
// speedup vs baseline: 2.0269x; 1.1281x over previous
#include <cuda_runtime.h>
#include <cuda_fp16.h>
#include <cuda_bf16.h>
#include <stdint.h>

#define N_NODES 100000
#define N_EDGES 1600000
#define DIM 128
#define SCAN_B 1024
#define SCAN_NB ((N_NODES + SCAN_B - 1) / SCAN_B)   // 98

// ---------------- scratch (no allocations allowed) ----------------
__device__ int    g_deg[N_NODES];
__device__ int    g_off[N_NODES];
__device__ int    g_cur[N_NODES];
__device__ int    g_bsums[SCAN_NB];
__device__ int    g_srcs[N_EDGES];
__device__ float  g_bufY[(size_t)N_NODES * DIM];           // GEMM out fp32
__device__ __half g_bufY16[(size_t)N_NODES * DIM];         // GEMM out fp16 (gather)
__device__ __nv_bfloat16 g_bufHh[(size_t)N_NODES * DIM];   // h hi (next GEMM A)
__device__ __nv_bfloat16 g_bufHl[(size_t)N_NODES * DIM];   // h lo
__device__ __nv_bfloat16 g_W1h[128 * 128], g_W1l[128 * 128];
__device__ __nv_bfloat16 g_Wmh[128 * 128], g_Wml[128 * 128];
__device__ __nv_bfloat16 g_W2h[128 * 64],  g_W2l[128 * 64];

// ---------------- CSR construction ----------------
__global__ void k_zero_deg() {
    int i = blockIdx.x * blockDim.x + threadIdx.x;
    if (i < N_NODES) g_deg[i] = 0;
}

__global__ void k_hist(const int* __restrict__ ei) {
    int e = blockIdx.x * blockDim.x + threadIdx.x;
    if (e < N_EDGES) {
        int d = ei[N_EDGES + e];
        if (d >= 0 && d < N_NODES) atomicAdd(&g_deg[d], 1);
    }
}

__global__ void k_scan1() {
    __shared__ int s[SCAN_B];
    int tid = threadIdx.x;
    int i = blockIdx.x * SCAN_B + tid;
    int v = (i < N_NODES) ? g_deg[i] : 0;
    s[tid] = v;
    __syncthreads();
    #pragma unroll
    for (int d = 1; d < SCAN_B; d <<= 1) {
        int t = (tid >= d) ? s[tid - d] : 0;
        __syncthreads();
        s[tid] += t;
        __syncthreads();
    }
    if (i < N_NODES) g_off[i] = s[tid] - v;
    if (tid == SCAN_B - 1) g_bsums[blockIdx.x] = s[tid];
}

__global__ void k_scan2() {
    __shared__ int red[32];
    int tid = threadIdx.x;
    int v = (tid < (int)blockIdx.x && tid < SCAN_NB) ? g_bsums[tid] : 0;
    #pragma unroll
    for (int o = 16; o > 0; o >>= 1) v += __shfl_down_sync(0xffffffffu, v, o);
    if ((tid & 31) == 0) red[tid >> 5] = v;
    __syncthreads();
    if (tid < 32) {
        int r = (tid < (int)(blockDim.x >> 5)) ? red[tid] : 0;
        #pragma unroll
        for (int o = 16; o > 0; o >>= 1) r += __shfl_down_sync(0xffffffffu, r, o);
        if (tid == 0) red[0] = r;
    }
    __syncthreads();
    int base = red[0];
    int i = blockIdx.x * SCAN_B + tid;
    if (i < N_NODES) {
        int o = g_off[i] + base;
        g_off[i] = o;
        g_cur[i] = o;
    }
}

__global__ void k_scatter(const int* __restrict__ ei) {
    int e = blockIdx.x * blockDim.x + threadIdx.x;
    if (e < N_EDGES) {
        int d = ei[N_EDGES + e];
        int s = ei[e];
        if (d >= 0 && d < N_NODES && s >= 0 && s < N_NODES) {
            int pos = atomicAdd(&g_cur[d], 1);
            g_srcs[pos] = s;
        }
    }
}

// ---------------- helpers ----------------
__device__ __forceinline__ unsigned cvta_s(const void* p) {
    return (unsigned)__cvta_generic_to_shared(p);
}
__device__ __forceinline__ void ldsm_x4(unsigned& r0, unsigned& r1,
                                        unsigned& r2, unsigned& r3, unsigned a) {
    asm volatile("ldmatrix.sync.aligned.m8n8.x4.shared.b16 {%0,%1,%2,%3}, [%4];"
                 : "=r"(r0), "=r"(r1), "=r"(r2), "=r"(r3) : "r"(a));
}
__device__ __forceinline__ void ldsm_x2t(unsigned& r0, unsigned& r1, unsigned a) {
    asm volatile("ldmatrix.sync.aligned.m8n8.x2.trans.shared.b16 {%0,%1}, [%2];"
                 : "=r"(r0), "=r"(r1) : "r"(a));
}
__device__ __forceinline__ void mma_bf16(float* c, unsigned a0, unsigned a1,
                                         unsigned a2, unsigned a3,
                                         unsigned b0, unsigned b1) {
    asm volatile(
        "mma.sync.aligned.m16n8k16.row.col.f32.bf16.bf16.f32 "
        "{%0,%1,%2,%3}, {%4,%5,%6,%7}, {%8,%9}, {%0,%1,%2,%3};"
        : "+f"(c[0]), "+f"(c[1]), "+f"(c[2]), "+f"(c[3])
        : "r"(a0), "r"(a1), "r"(a2), "r"(a3), "r"(b0), "r"(b1));
}
__device__ __forceinline__ unsigned pack_bf16(__nv_bfloat16 a, __nv_bfloat16 b) {
    __nv_bfloat162 p; p.x = a; p.y = b;
    return *reinterpret_cast<unsigned*>(&p);
}
__device__ __forceinline__ void bsplit(float f, __nv_bfloat16& h, __nv_bfloat16& l) {
    h = __float2bfloat16_rn(f);
    l = __float2bfloat16_rn(f - __bfloat162float(h));
}

// ---------------- W preconversion: fp32 -> bf16 hi/lo ----------------
__global__ void k_wconv(const float* __restrict__ W, __nv_bfloat16* __restrict__ Wh,
                        __nv_bfloat16* __restrict__ Wl, int n) {
    int i = blockIdx.x * blockDim.x + threadIdx.x;
    if (i < n) {
        float f = W[i];
        __nv_bfloat16 h, l;
        bsplit(f, h, l);
        Wh[i] = h; Wl[i] = l;
    }
}

// ---------------- GEMM (tensor core, bf16-split): Y = A[N,128] @ W[128,DOUT]
// A either fp32 (converted in prologue) or preconverted bf16 hi/lo.
template <int DOUT, bool A_SPLIT>
__global__ void __launch_bounds__(256, 2)
k_gemm_tc(const float* __restrict__ X,
          const __nv_bfloat16* __restrict__ Xh, const __nv_bfloat16* __restrict__ Xl,
          const __nv_bfloat16* __restrict__ Wh, const __nv_bfloat16* __restrict__ Wl,
          float* __restrict__ Y, __half* __restrict__ Y16) {
    constexpr int TROWS = (DOUT == 128) ? 64 : 128;
    constexpr int LDA = 136;
    constexpr int LDB = DOUT + 8;
    extern __shared__ __nv_bfloat16 sm[];
    __nv_bfloat16* sAh = sm;
    __nv_bfloat16* sAl = sAh + TROWS * LDA;
    __nv_bfloat16* sWh = sAl + TROWS * LDA;
    __nv_bfloat16* sWl = sWh + 128 * LDB;

    int tid = threadIdx.x, wid = tid >> 5, lane = tid & 31;
    int g = lane >> 2, tg = lane & 3;
    int rowBase = blockIdx.x * TROWS;

    if constexpr (A_SPLIT) {
        // pure bf16 copy: TROWS rows x 16 uint4 (8 bf16 each)
        for (int i = tid; i < TROWS * 16; i += 256) {
            int r = i >> 4, c8 = i & 15;
            int row = rowBase + r;
            uint4 vh = make_uint4(0, 0, 0, 0), vl = make_uint4(0, 0, 0, 0);
            if (row < N_NODES) {
                vh = __ldg((const uint4*)(Xh + (size_t)row * 128) + c8);
                vl = __ldg((const uint4*)(Xl + (size_t)row * 128) + c8);
            }
            int off = r * LDA + c8 * 8;
            *(uint4*)(sAh + off) = vh;
            *(uint4*)(sAl + off) = vl;
        }
    } else {
        for (int i = tid; i < TROWS * 32; i += 256) {
            int r = i >> 5, c4 = i & 31;
            int row = rowBase + r;
            float4 v = make_float4(0.f, 0.f, 0.f, 0.f);
            if (row < N_NODES)
                v = __ldg((const float4*)(X + (size_t)row * 128) + c4);
            __nv_bfloat16 h0, h1, h2, h3, l0, l1, l2, l3;
            bsplit(v.x, h0, l0); bsplit(v.y, h1, l1);
            bsplit(v.z, h2, l2); bsplit(v.w, h3, l3);
            int off = r * LDA + c4 * 4;
            *(uint2*)(sAh + off) = make_uint2(pack_bf16(h0, h1), pack_bf16(h2, h3));
            *(uint2*)(sAl + off) = make_uint2(pack_bf16(l0, l1), pack_bf16(l2, l3));
        }
    }
    // W: preconverted bf16 hi/lo, pure copy (128 x DOUT, 8 bf16 per uint4)
    for (int i = tid; i < 128 * (DOUT / 8); i += 256) {
        int k = i / (DOUT / 8), n8 = i % (DOUT / 8);
        uint4 vh = __ldg((const uint4*)(Wh + (size_t)k * DOUT) + n8);
        uint4 vl = __ldg((const uint4*)(Wl + (size_t)k * DOUT) + n8);
        int off = k * LDB + n8 * 8;
        *(uint4*)(sWh + off) = vh;
        *(uint4*)(sWl + off) = vl;
    }
    __syncthreads();

    int rg, n0;
    if constexpr (DOUT == 128) { rg = wid >> 1; n0 = (wid & 1) * 64; }
    else                       { rg = wid;      n0 = 0; }
    int r0 = rg * 16;

    float acc[8][4];
    #pragma unroll
    for (int i = 0; i < 8; ++i)
        #pragma unroll
        for (int j = 0; j < 4; ++j) acc[i][j] = 0.f;

    int arow = r0 + (lane & 15);
    int acolo = (lane >> 4) * 8;
    unsigned aH = cvta_s(sAh) + (unsigned)((arow * LDA + acolo) * 2);
    unsigned aL = cvta_s(sAl) + (unsigned)((arow * LDA + acolo) * 2);
    int brow = lane & 15;
    unsigned bH = cvta_s(sWh) + (unsigned)((brow * LDB + n0) * 2);
    unsigned bL = cvta_s(sWl) + (unsigned)((brow * LDB + n0) * 2);

    #pragma unroll
    for (int ks = 0; ks < 8; ++ks) {
        int k0 = ks * 16;
        unsigned ah0, ah1, ah2, ah3, al0, al1, al2, al3;
        ldsm_x4(ah0, ah1, ah2, ah3, aH + (unsigned)(k0 * 2));
        ldsm_x4(al0, al1, al2, al3, aL + (unsigned)(k0 * 2));
        unsigned bkoff = (unsigned)(k0 * LDB * 2);
        #pragma unroll
        for (int nt = 0; nt < 8; ++nt) {
            unsigned noff = bkoff + (unsigned)(nt * 8 * 2);
            unsigned bh0, bh1, bl0, bl1;
            ldsm_x2t(bh0, bh1, bH + noff);
            ldsm_x2t(bl0, bl1, bL + noff);
            mma_bf16(acc[nt], ah0, ah1, ah2, ah3, bh0, bh1);
            mma_bf16(acc[nt], al0, al1, al2, al3, bh0, bh1);
            mma_bf16(acc[nt], ah0, ah1, ah2, ah3, bl0, bl1);
        }
    }

    int row0 = rowBase + r0 + g;
    int row1 = row0 + 8;
    #pragma unroll
    for (int nt = 0; nt < 8; ++nt) {
        int col = n0 + nt * 8 + tg * 2;
        if (row0 < N_NODES) {
            *(float2*)(Y + (size_t)row0 * DOUT + col) = make_float2(acc[nt][0], acc[nt][1]);
            __half2 hh = __floats2half2_rn(acc[nt][0], acc[nt][1]);
            *(unsigned*)(Y16 + (size_t)row0 * DOUT + col) = *(const unsigned*)&hh;
        }
        if (row1 < N_NODES) {
            *(float2*)(Y + (size_t)row1 * DOUT + col) = make_float2(acc[nt][2], acc[nt][3]);
            __half2 hh = __floats2half2_rn(acc[nt][2], acc[nt][3]);
            *(unsigned*)(Y16 + (size_t)row1 * DOUT + col) = *(const unsigned*)&hh;
        }
    }
}

// ---------- fused aggregate + bias (+relu); output fp32 OR bf16 hi/lo split
template <int D, bool RELU, bool SPLIT_OUT>
__global__ void k_agg_post(const float* __restrict__ y,
                           const __half* __restrict__ y16,
                           const float* __restrict__ bias,
                           float* __restrict__ out,
                           __nv_bfloat16* __restrict__ outh,
                           __nv_bfloat16* __restrict__ outl) {
    int gw = (blockIdx.x * blockDim.x + threadIdx.x) >> 5;
    int lane = threadIdx.x & 31;
    if (gw >= N_NODES) return;
    int beg = g_off[gw];
    int end = beg + g_deg[gw];

    if constexpr (D == 128) {
        float4 acc = __ldg((const float4*)(y + (size_t)gw * 128) + lane);
        float4 acc2 = make_float4(0.f, 0.f, 0.f, 0.f);
        int e = beg;
        for (; e + 3 < end; e += 4) {
            int s0 = g_srcs[e],     s1 = g_srcs[e + 1];
            int s2 = g_srcs[e + 2], s3 = g_srcs[e + 3];
            uint2 u0 = __ldg((const uint2*)(y16 + (size_t)s0 * 128) + lane);
            uint2 u1 = __ldg((const uint2*)(y16 + (size_t)s1 * 128) + lane);
            uint2 u2 = __ldg((const uint2*)(y16 + (size_t)s2 * 128) + lane);
            uint2 u3 = __ldg((const uint2*)(y16 + (size_t)s3 * 128) + lane);
            float2 a0 = __half22float2(*(const __half2*)&u0.x);
            float2 b0 = __half22float2(*(const __half2*)&u0.y);
            float2 a1 = __half22float2(*(const __half2*)&u1.x);
            float2 b1 = __half22float2(*(const __half2*)&u1.y);
            float2 a2 = __half22float2(*(const __half2*)&u2.x);
            float2 b2 = __half22float2(*(const __half2*)&u2.y);
            float2 a3 = __half22float2(*(const __half2*)&u3.x);
            float2 b3 = __half22float2(*(const __half2*)&u3.y);
            acc.x  += a0.x + a1.x; acc.y  += a0.y + a1.y;
            acc.z  += b0.x + b1.x; acc.w  += b0.y + b1.y;
            acc2.x += a2.x + a3.x; acc2.y += a2.y + a3.y;
            acc2.z += b2.x + b3.x; acc2.w += b2.y + b3.y;
        }
        for (; e < end; ++e) {
            int s = g_srcs[e];
            uint2 u = __ldg((const uint2*)(y16 + (size_t)s * 128) + lane);
            float2 a = __half22float2(*(const __half2*)&u.x);
            float2 b = __half22float2(*(const __half2*)&u.y);
            acc.x += a.x; acc.y += a.y; acc.z += b.x; acc.w += b.y;
        }
        acc.x += acc2.x; acc.y += acc2.y; acc.z += acc2.z; acc.w += acc2.w;
        float4 bb = __ldg((const float4*)bias + lane);
        acc.x += bb.x; acc.y += bb.y; acc.z += bb.z; acc.w += bb.w;
        if (RELU) {
            acc.x = fmaxf(acc.x, 0.f); acc.y = fmaxf(acc.y, 0.f);
            acc.z = fmaxf(acc.z, 0.f); acc.w = fmaxf(acc.w, 0.f);
        }
        if constexpr (SPLIT_OUT) {
            __nv_bfloat16 h0, h1, h2, h3, l0, l1, l2, l3;
            bsplit(acc.x, h0, l0); bsplit(acc.y, h1, l1);
            bsplit(acc.z, h2, l2); bsplit(acc.w, h3, l3);
            ((uint2*)(outh + (size_t)gw * 128))[lane] =
                make_uint2(pack_bf16(h0, h1), pack_bf16(h2, h3));
            ((uint2*)(outl + (size_t)gw * 128))[lane] =
                make_uint2(pack_bf16(l0, l1), pack_bf16(l2, l3));
        } else {
            ((float4*)(out + (size_t)gw * 128))[lane] = acc;
        }
    } else {
        float2 acc = __ldg((const float2*)(y + (size_t)gw * 64) + lane);
        float2 acc2 = make_float2(0.f, 0.f);
        int e = beg;
        for (; e + 3 < end; e += 4) {
            int s0 = g_srcs[e],     s1 = g_srcs[e + 1];
            int s2 = g_srcs[e + 2], s3 = g_srcs[e + 3];
            unsigned u0 = __ldg((const unsigned*)(y16 + (size_t)s0 * 64) + lane);
            unsigned u1 = __ldg((const unsigned*)(y16 + (size_t)s1 * 64) + lane);
            unsigned u2 = __ldg((const unsigned*)(y16 + (size_t)s2 * 64) + lane);
            unsigned u3 = __ldg((const unsigned*)(y16 + (size_t)s3 * 64) + lane);
            float2 a0 = __half22float2(*(const __half2*)&u0);
            float2 a1 = __half22float2(*(const __half2*)&u1);
            float2 a2 = __half22float2(*(const __half2*)&u2);
            float2 a3 = __half22float2(*(const __half2*)&u3);
            acc.x  += a0.x + a1.x; acc.y  += a0.y + a1.y;
            acc2.x += a2.x + a3.x; acc2.y += a2.y + a3.y;
        }
        for (; e < end; ++e) {
            int s = g_srcs[e];
            unsigned u = __ldg((const unsigned*)(y16 + (size_t)s * 64) + lane);
            float2 a = __half22float2(*(const __half2*)&u);
            acc.x += a.x; acc.y += a.y;
        }
        acc.x += acc2.x; acc.y += acc2.y;
        float2 bb = __ldg((const float2*)bias + lane);
        acc.x += bb.x; acc.y += bb.y;
        if (RELU) { acc.x = fmaxf(acc.x, 0.f); acc.y = fmaxf(acc.y, 0.f); }
        ((float2*)(out + (size_t)gw * 64))[lane] = acc;
    }
}

// ---------------- launch ----------------
extern "C" void kernel_launch(void* const* d_in, const int* in_sizes, int n_in,
                              void* d_out, int out_size) {
    const float* x  = (const float*)d_in[0];
    const int*   ei = (const int*)d_in[1];
    const float* W1 = (const float*)d_in[2];
    const float* b1 = (const float*)d_in[3];
    const float* Wm = (const float*)d_in[4];
    const float* bm = (const float*)d_in[5];
    const float* W2 = (const float*)d_in[6];
    const float* b2 = (const float*)d_in[7];
    float* out = (float*)d_out;

    const int smem128 = (64 * 136 * 2 + 128 * 136 * 2) * 2;   // 104448
    const int smem64  = (128 * 136 * 2 + 128 * 72 * 2) * 2;   // 106496

    static bool initDone = false;
    static cudaStream_t s2 = nullptr;
    static cudaEvent_t evFork = nullptr, evJoin = nullptr;
    if (!initDone) {
        cudaFuncSetAttribute(k_gemm_tc<128, false>,
                             cudaFuncAttributeMaxDynamicSharedMemorySize, smem128);
        cudaFuncSetAttribute(k_gemm_tc<128, true>,
                             cudaFuncAttributeMaxDynamicSharedMemorySize, smem128);
        cudaFuncSetAttribute(k_gemm_tc<64, true>,
                             cudaFuncAttributeMaxDynamicSharedMemorySize, smem64);
        cudaStreamCreateWithFlags(&s2, cudaStreamNonBlocking);
        cudaEventCreateWithFlags(&evFork, cudaEventDisableTiming);
        cudaEventCreateWithFlags(&evJoin, cudaEventDisableTiming);
        initDone = true;
    }

    float* bufY = nullptr; __half* bufY16 = nullptr;
    __nv_bfloat16 *bufHh = nullptr, *bufHl = nullptr;
    __nv_bfloat16 *w1h, *w1l, *wmh, *wml, *w2h, *w2l;
    cudaGetSymbolAddress((void**)&bufY, g_bufY);
    cudaGetSymbolAddress((void**)&bufY16, g_bufY16);
    cudaGetSymbolAddress((void**)&bufHh, g_bufHh);
    cudaGetSymbolAddress((void**)&bufHl, g_bufHl);
    cudaGetSymbolAddress((void**)&w1h, g_W1h); cudaGetSymbolAddress((void**)&w1l, g_W1l);
    cudaGetSymbolAddress((void**)&wmh, g_Wmh); cudaGetSymbolAddress((void**)&wml, g_Wml);
    cudaGetSymbolAddress((void**)&w2h, g_W2h); cudaGetSymbolAddress((void**)&w2l, g_W2l);

    const int aggBlocks = (N_NODES + 7) / 8;
    const int gemmB128  = (N_NODES + 63) / 64;
    const int gemmB64   = (N_NODES + 127) / 128;

    // ---- fork: Wm/W2 conversion + CSR build on s2 ----
    cudaEventRecord(evFork, 0);
    cudaStreamWaitEvent(s2, evFork, 0);

    k_wconv<<<(128 * 128 + 255) / 256, 256, 0, s2>>>(Wm, wmh, wml, 128 * 128);
    k_wconv<<<(128 * 64 + 255) / 256, 256, 0, s2>>>(W2, w2h, w2l, 128 * 64);
    k_zero_deg<<<(N_NODES + 255) / 256, 256, 0, s2>>>();
    k_hist<<<(N_EDGES + 255) / 256, 256, 0, s2>>>(ei);
    k_scan1<<<SCAN_NB, SCAN_B, 0, s2>>>();
    k_scan2<<<SCAN_NB, SCAN_B, 0, s2>>>();
    k_scatter<<<(N_EDGES + 255) / 256, 256, 0, s2>>>(ei);
    cudaEventRecord(evJoin, s2);

    // main stream: W1 conversion + layer-1 GEMM (A fp32 conversion in prologue)
    k_wconv<<<(128 * 128 + 255) / 256, 256>>>(W1, w1h, w1l, 128 * 128);
    k_gemm_tc<128, false><<<gemmB128, 256, smem128>>>(
        x, nullptr, nullptr, w1h, w1l, bufY, bufY16);

    cudaStreamWaitEvent(0, evJoin, 0);

    // layer 1 agg -> bf16 split h
    k_agg_post<128, true, true><<<aggBlocks, 256>>>(
        bufY, bufY16, b1, nullptr, bufHh, bufHl);

    // layer 2
    k_gemm_tc<128, true><<<gemmB128, 256, smem128>>>(
        nullptr, bufHh, bufHl, wmh, wml, bufY, bufY16);
    k_agg_post<128, true, true><<<aggBlocks, 256>>>(
        bufY, bufY16, bm, nullptr, bufHh, bufHl);

    // layer 3 (64-dim)
    k_gemm_tc<64, true><<<gemmB64, 256, smem64>>>(
        nullptr, bufHh, bufHl, w2h, w2l, bufY, bufY16);
    k_agg_post<64, false, false><<<aggBlocks, 256>>>(
        bufY, bufY16, b2, out, nullptr, nullptr);

    (void)in_sizes; (void)n_in; (void)out_size;
}